// round 13
// baseline (speedup 1.0000x reference)
#include <cuda_runtime.h>
#include <cuda_fp16.h>
#include <math.h>
#include <stdint.h>

// Problem constants (fixed by the reference)
#define T_LEN 128
#define B_ENV 4096
#define N_TOT (T_LEN * B_ENV)   // 524288
#define HID   128
#define NA    6

// ---------------------------------------------------------------------------
// Scratch (device globals — no runtime allocation allowed)
// ---------------------------------------------------------------------------
__device__ __half g_gxh[(size_t)N_TOT * 512]; // 512 MB  x-gates (fp16)
__device__ float g_wg[36 * 512];              // combined gx weight, k-major
__device__ float g_bg[512];                   // combined gate bias
__device__ float g_whT[HID * 512];            // Whh transposed: [k][j]

// ---------------------------------------------------------------------------
// Packed f32x2 helpers
// ---------------------------------------------------------------------------
typedef unsigned long long u64;
__device__ __forceinline__ u64 pack2(float lo, float hi) {
    u64 r; asm("mov.b64 %0, {%1, %2};" : "=l"(r) : "f"(lo), "f"(hi)); return r;
}
__device__ __forceinline__ u64 dup2(float x) {
    u64 r; asm("mov.b64 %0, {%1, %1};" : "=l"(r) : "f"(x)); return r;
}
__device__ __forceinline__ void fma2(u64& acc, u64 a, u64 b) {
    asm("fma.rn.f32x2 %0, %1, %2, %0;" : "+l"(acc) : "l"(a), "l"(b));
}
__device__ __forceinline__ u64 fma2o(u64 a, u64 b, u64 c) {
    u64 r; asm("fma.rn.f32x2 %0, %1, %2, %3;" : "=l"(r) : "l"(a), "l"(b), "l"(c));
    return r;
}
__device__ __forceinline__ void unpack2(u64 v, float& lo, float& hi) {
    asm("mov.b64 {%0, %1}, %2;" : "=f"(lo), "=f"(hi) : "l"(v));
}
// Hardware tanh (MUFU.TANH, sm_75+ base ISA)
__device__ __forceinline__ float ftanh(float x) {
    float y; asm("tanh.approx.f32 %0, %1;" : "=f"(y) : "f"(x)); return y;
}
__device__ __forceinline__ float fsig(float x) {
    return fmaf(0.5f, ftanh(0.5f * x), 0.5f);
}
// pack two f32 into f16x2 (lo, hi)
__device__ __forceinline__ uint32_t f16x2(float lo, float hi) {
    uint32_t r;
    asm("cvt.rn.f16x2.f32 %0, %1, %2;" : "=r"(r) : "f"(hi), "f"(lo));
    return r;
}

// ---------------------------------------------------------------------------
// Weight prep
// ---------------------------------------------------------------------------
__global__ void prep_wg(const float* __restrict__ Wih, const float* __restrict__ Wl,
                        const float* __restrict__ We, float* __restrict__ out)
{
    int idx = blockIdx.x * 256 + threadIdx.x;
    if (idx >= 36 * 512) return;
    int k = idx >> 9, n = idx & 511;
    float v = 0.f;
    if (k < 32) {
        v = Wih[n * 96 + k];
    } else if (k < 34) {
        int d = k - 32;
        float s = 0.f;
        for (int j = 0; j < 32; j++) s += Wl[d * 32 + j] * Wih[n * 96 + 32 + j];
        v = s * 0.1f;
    } else if (k == 34) {
        float s = 0.f;
        for (int j = 0; j < 32; j++) s += We[j] * Wih[n * 96 + 64 + j];
        v = s * (1.f / 200.f);
    }
    out[k * 512 + n] = v;
}

__global__ void prep_bg(const float* __restrict__ Wih, const float* __restrict__ bl,
                        const float* __restrict__ be, const float* __restrict__ bih,
                        const float* __restrict__ bhh, float* __restrict__ bg)
{
    int n = blockIdx.x * 256 + threadIdx.x;
    if (n >= 512) return;
    float s = bih[n] + bhh[n];
    for (int j = 0; j < 32; j++)
        s += bl[j] * Wih[n * 96 + 32 + j] + be[j] * Wih[n * 96 + 64 + j];
    bg[n] = s;
}

__global__ void prep_whT(const float* __restrict__ Whh, float* __restrict__ whT)
{
    int idx = blockIdx.x * 256 + threadIdx.x;
    if (idx >= HID * 512) return;
    int k = idx >> 9, j = idx & 511;
    whT[idx] = Whh[j * HID + k];
}

// ---------------------------------------------------------------------------
// MEGA encoder: image -> f1 -> f2 -> f3 -> f4(+loc/eng) -> gx(fp16), ONE kernel.
// ---------------------------------------------------------------------------
#define SS 132

__global__ __launch_bounds__(512) void mega_enc(
    const float* __restrict__ img, const float* __restrict__ loc,
    const float* __restrict__ eng,
    const float* __restrict__ W1, const float* __restrict__ b1,
    const float* __restrict__ W2, const float* __restrict__ b2,
    const float* __restrict__ W3, const float* __restrict__ b3,
    const float* __restrict__ W4, const float* __restrict__ b4,
    const float* __restrict__ wg, const float* __restrict__ bg,
    __half* __restrict__ gxh)
{
    extern __shared__ float sm[];
    float* fA   = sm;                    // [256][SS]
    float* faux = fA + 256 * SS;         // [36][SS]
    float* bs   = faux + 36 * SS;        // [32][264]

    const int tid = threadIdx.x;
    const int rowBase = blockIdx.x * 128;

    for (int i = tid; i < 128 * 25; i += 512) {
        int k = i % 25, m = i / 25;
        faux[k * SS + m] = img[(size_t)(rowBase + m) * 25 + k] * (1.f / 255.f);
    }
    for (int i = tid; i < 25 * 256; i += 512) {
        int k = i >> 8, n = i & 255;
        bs[k * 264 + n] = W1[i];
    }
    __syncthreads();

    // ================= phase 1: f1 = relu(x @ W1 + b1), K=25 =================
    {
        const int rg = tid >> 6;
        const int cg = tid & 63;
        u64 acc[8][4];
#pragma unroll
        for (int p = 0; p < 8; p++)
#pragma unroll
            for (int j = 0; j < 4; j++) acc[p][j] = 0ull;

        for (int k = 0; k < 25; k++) {
            const ulonglong2* ap = (const ulonglong2*)(faux + k * SS + rg * 16);
            ulonglong2 A0 = ap[0], A1 = ap[1], A2 = ap[2], A3 = ap[3];
            u64 av[8] = {A0.x, A0.y, A1.x, A1.y, A2.x, A2.y, A3.x, A3.y};
            float4 q = *(const float4*)(bs + k * 264 + cg * 4);
            float bv[4] = {q.x, q.y, q.z, q.w};
#pragma unroll
            for (int j = 0; j < 4; j++) {
                u64 bd = dup2(bv[j]);
#pragma unroll
                for (int p = 0; p < 8; p++) fma2(acc[p][j], av[p], bd);
            }
        }
        float4 c1 = *(const float4*)(b1 + cg * 4);
        float bias1[4] = {c1.x, c1.y, c1.z, c1.w};
        __syncthreads();
#pragma unroll
        for (int p = 0; p < 8; p++) {
            int m0 = rg * 16 + 2 * p;
#pragma unroll
            for (int j = 0; j < 4; j++) {
                float o0, o1;
                unpack2(acc[p][j], o0, o1);
                o0 = fmaxf(o0 + bias1[j], 0.f);
                o1 = fmaxf(o1 + bias1[j], 0.f);
                *(u64*)&fA[(cg * 4 + j) * SS + m0] = pack2(o0, o1);
            }
        }
    }

    // ================= phase 2: f2 = relu(f1 @ W2 + b2), K=256 ================
    {
        const int rg = tid >> 6;
        const int cg = tid & 63;
        float ldr[8];
#define LOADW2(c)                                                      \
    _Pragma("unroll") for (int i = 0; i < 8; i++) {                    \
        int idx = tid + i * 512;                                       \
        int k = idx >> 8, n = idx & 255;                               \
        ldr[i] = W2[(size_t)((c) * 16 + k) * 256 + n];                 \
    }
#define STW2(buf)                                                      \
    _Pragma("unroll") for (int i = 0; i < 8; i++) {                    \
        int idx = tid + i * 512;                                       \
        int k = idx >> 8, n = idx & 255;                               \
        bs[((buf) * 16 + k) * 264 + n] = ldr[i];                       \
    }
        LOADW2(0);
        __syncthreads();
        STW2(0);
        __syncthreads();

        u64 acc[8][4];
#pragma unroll
        for (int p = 0; p < 8; p++)
#pragma unroll
            for (int j = 0; j < 4; j++) acc[p][j] = 0ull;

        for (int c = 0; c < 16; c++) {
            if (c < 15) { LOADW2(c + 1); }
            const float* bsc = bs + (c & 1) * 16 * 264;
            const float* f1c = fA + c * 16 * SS;
#pragma unroll
            for (int k = 0; k < 16; k++) {
                const ulonglong2* ap = (const ulonglong2*)(f1c + k * SS + rg * 16);
                ulonglong2 A0 = ap[0], A1 = ap[1], A2 = ap[2], A3 = ap[3];
                u64 av[8] = {A0.x, A0.y, A1.x, A1.y, A2.x, A2.y, A3.x, A3.y};
                float4 q = *(const float4*)(bsc + k * 264 + cg * 4);
                float bv[4] = {q.x, q.y, q.z, q.w};
#pragma unroll
                for (int j = 0; j < 4; j++) {
                    u64 bd = dup2(bv[j]);
#pragma unroll
                    for (int p = 0; p < 8; p++) fma2(acc[p][j], av[p], bd);
                }
            }
            if (c < 15) { STW2((c + 1) & 1); }
            __syncthreads();
        }
#undef LOADW2
#undef STW2
        float4 c2 = *(const float4*)(b2 + cg * 4);
        float bias2[4] = {c2.x, c2.y, c2.z, c2.w};
#pragma unroll
        for (int p = 0; p < 8; p++) {
            int m0 = rg * 16 + 2 * p;
#pragma unroll
            for (int j = 0; j < 4; j++) {
                float o0, o1;
                unpack2(acc[p][j], o0, o1);
                o0 = fmaxf(o0 + bias2[j], 0.f);
                o1 = fmaxf(o1 + bias2[j], 0.f);
                *(u64*)&fA[(cg * 4 + j) * SS + m0] = pack2(o0, o1);
            }
        }
    }
    __syncthreads();

    // ================= phase 3: f3 = relu(f2 @ W3 + b3), K=256 ================
    {
        const int rg = tid >> 5;
        const int cg = tid & 31;
        float ldr[4];
#define LOADW3(c)                                                      \
    _Pragma("unroll") for (int i = 0; i < 4; i++) {                    \
        int idx = tid + i * 512;                                       \
        int k = idx >> 7, n = idx & 127;                               \
        ldr[i] = W3[(size_t)((c) * 16 + k) * 128 + n];                 \
    }
#define STW3(buf)                                                      \
    _Pragma("unroll") for (int i = 0; i < 4; i++) {                    \
        int idx = tid + i * 512;                                       \
        int k = idx >> 7, n = idx & 127;                               \
        bs[((buf) * 16 + k) * 132 + n] = ldr[i];                       \
    }
        LOADW3(0);
        STW3(0);
        __syncthreads();

        u64 acc[4][4];
#pragma unroll
        for (int p = 0; p < 4; p++)
#pragma unroll
            for (int j = 0; j < 4; j++) acc[p][j] = 0ull;

        for (int c = 0; c < 16; c++) {
            if (c < 15) { LOADW3(c + 1); }
            const float* bsc = bs + (c & 1) * 16 * 132;
            const float* f2c = fA + c * 16 * SS;
#pragma unroll
            for (int k = 0; k < 16; k++) {
                const ulonglong2* ap = (const ulonglong2*)(f2c + k * SS + rg * 8);
                ulonglong2 A0 = ap[0], A1 = ap[1];
                u64 av[4] = {A0.x, A0.y, A1.x, A1.y};
                float4 q = *(const float4*)(bsc + k * 132 + cg * 4);
                float bv[4] = {q.x, q.y, q.z, q.w};
#pragma unroll
                for (int j = 0; j < 4; j++) {
                    u64 bd = dup2(bv[j]);
#pragma unroll
                    for (int p = 0; p < 4; p++) fma2(acc[p][j], av[p], bd);
                }
            }
            if (c < 15) { STW3((c + 1) & 1); }
            __syncthreads();
        }
#undef LOADW3
#undef STW3
        float4 cb = *(const float4*)(b3 + cg * 4);
        float bias3[4] = {cb.x, cb.y, cb.z, cb.w};
#pragma unroll
        for (int p = 0; p < 4; p++) {
            int m0 = rg * 8 + 2 * p;
#pragma unroll
            for (int j = 0; j < 4; j++) {
                float o0, o1;
                unpack2(acc[p][j], o0, o1);
                o0 = fmaxf(o0 + bias3[j], 0.f);
                o1 = fmaxf(o1 + bias3[j], 0.f);
                *(u64*)&fA[(cg * 4 + j) * SS + m0] = pack2(o0, o1);
            }
        }
    }
    __syncthreads();

    // ================= phase 4: f4 = relu(f3 @ W4 + b4), K=128 ================
    {
        const int tr4 = tid >> 3;
        const int tc4 = tid & 7;
        u64 acc[4] = {0ull, 0ull, 0ull, 0ull};
#pragma unroll 4
        for (int k = 0; k < 128; k++) {
            u64 a = *(const u64*)&fA[k * SS + tr4 * 2];
            float4 q = *(const float4*)&W4[k * 32 + tc4 * 4];
            float bv[4] = {q.x, q.y, q.z, q.w};
#pragma unroll
            for (int j = 0; j < 4; j++) fma2(acc[j], a, dup2(bv[j]));
        }
        float4 cb = *(const float4*)(b4 + tc4 * 4);
        float bias4[4] = {cb.x, cb.y, cb.z, cb.w};
        __syncthreads();
#pragma unroll
        for (int j = 0; j < 4; j++) {
            float o0, o1;
            unpack2(acc[j], o0, o1);
            o0 = fmaxf(o0 + bias4[j], 0.f);
            o1 = fmaxf(o1 + bias4[j], 0.f);
            *(u64*)&faux[(tc4 * 4 + j) * SS + tr4 * 2] = pack2(o0, o1);
        }
        if (tid < 128) {
            int n = rowBase + tid;
            faux[32 * SS + tid] = loc[2 * n];
            faux[33 * SS + tid] = loc[2 * n + 1];
            faux[34 * SS + tid] = eng[n];
            faux[35 * SS + tid] = 0.f;
        }
    }
    __syncthreads();

    // ============ phase gx: gates = f4e @ Wg + bg -> fp16, K=36 ============
    {
        const int rg = tid >> 6;
        const int cg = tid & 63;
        for (int pc = 0; pc < 2; pc++) {
            u64 acc[8][4];
#pragma unroll
            for (int p = 0; p < 8; p++)
#pragma unroll
                for (int j = 0; j < 4; j++) acc[p][j] = 0ull;

#pragma unroll 4
            for (int k = 0; k < 36; k++) {
                const ulonglong2* ap = (const ulonglong2*)(faux + k * SS + rg * 16);
                ulonglong2 A0 = ap[0], A1 = ap[1], A2 = ap[2], A3 = ap[3];
                u64 av[8] = {A0.x, A0.y, A1.x, A1.y, A2.x, A2.y, A3.x, A3.y};
                float4 q = *(const float4*)&wg[k * 512 + pc * 256 + cg * 4];
                float bv[4] = {q.x, q.y, q.z, q.w};
#pragma unroll
                for (int j = 0; j < 4; j++) {
                    u64 bd = dup2(bv[j]);
#pragma unroll
                    for (int p = 0; p < 8; p++) fma2(acc[p][j], av[p], bd);
                }
            }
            float4 cb = *(const float4*)(bg + pc * 256 + cg * 4);
            float bias0[4] = {cb.x, cb.y, cb.z, cb.w};
#pragma unroll
            for (int p = 0; p < 8; p++) {
                int m0 = rowBase + rg * 16 + 2 * p;
                float o0[4], o1[4];
#pragma unroll
                for (int j = 0; j < 4; j++) {
                    unpack2(acc[p][j], o0[j], o1[j]);
                    o0[j] += bias0[j];
                    o1[j] += bias0[j];
                }
                uint2 v0 = make_uint2(f16x2(o0[0], o0[1]), f16x2(o0[2], o0[3]));
                uint2 v1 = make_uint2(f16x2(o1[0], o1[1]), f16x2(o1[2], o1[3]));
                *(uint2*)&gxh[(size_t)m0 * 512 + pc * 256 + cg * 4] = v0;
                *(uint2*)&gxh[(size_t)(m0 + 1) * 512 + pc * 256 + cg * 4] = v1;
            }
        }
    }
}

// ---------------------------------------------------------------------------
// LSTM v7: 32 rows/CTA (128 CTAs, 1/SM), coalesced WhhT, fp16 gx, heads fused
// (warps 0-6 compute heads(t-1) during the gates phase; no hs buffer).
// ---------------------------------------------------------------------------
#define LROWS 32
#define HS_STR 36
#define GS_STR 34

__global__ __launch_bounds__(512) void lstm_v7(
    const __half* __restrict__ gxh, const int* __restrict__ done,
    const float* __restrict__ h0, const float* __restrict__ c0,
    const float* __restrict__ whT,
    const float* __restrict__ Wa, const float* __restrict__ ba,
    const float* __restrict__ Wc, const float* __restrict__ bc,
    float* __restrict__ out)
{
    extern __shared__ float sm[];
    float* h_s = sm;                        // [HID][HS_STR]
    float* gs  = h_s + HID * HS_STR;        // [512][GS_STR]
    float* msall = gs + 512 * GS_STR;       // [T_LEN*32]
    float* whead = msall + T_LEN * 32;      // [HID*8]
    float* bsh   = whead + HID * 8;         // [8]

    const int tid = threadIdx.x;
    const int r0 = blockIdx.x * LROWS;
    const int r_h = tid / 7;                // head row (valid for tid<224)
    const int c_h = tid - r_h * 7;          // head col

    float creg[8];
#pragma unroll
    for (int i = 0; i < 8; i++) {
        int e = tid + i * 512;
        int k = e >> 5, r = e & 31;
        h_s[k * HS_STR + r] = h0[(r0 + r) * HID + k];
        creg[i] = c0[(r0 + r) * HID + k];
    }
#pragma unroll
    for (int i = 0; i < 8; i++) {
        int e = tid + i * 512;
        int t = e >> 5, r = e & 31;
        msall[e] = done[t * B_ENV + r0 + r] ? 0.f : 1.f;
    }
    for (int i = tid; i < HID * 8; i += 512) {
        int k = i >> 3, c = i & 7;
        float v = 0.f;
        if (c < NA) v = Wa[k * NA + c];
        else if (c == NA) v = Wc[k];
        whead[i] = v;
    }
    if (tid < 8) bsh[tid] = (tid < NA) ? ba[tid] : ((tid == NA) ? bc[0] : 0.f);
    __syncthreads();

    for (int t = 0; t < T_LEN; t++) {
        // ---- heads(t-1): warps 0-6 (224 threads), reads h_s only ----
        if (t > 0 && tid < LROWS * 7) {
            float s = bsh[c_h];
#pragma unroll 8
            for (int k = 0; k < HID; k++)
                s += h_s[k * HS_STR + r_h] * whead[k * 8 + c_h];
            out[((size_t)(t - 1) * B_ENV + r0) * 7 + tid] = s;
        }

        // ---- gates: thread j = tid computes gates[*, j] for 32 rows ----
        {
            const __half* gp = gxh + ((size_t)t * B_ENV + r0) * 512 + tid;
            u64 gxp[16];
#pragma unroll
            for (int p = 0; p < 16; p++)
                gxp[p] = pack2(__half2float(gp[(size_t)(2 * p) * 512]),
                               __half2float(gp[(size_t)(2 * p + 1) * 512]));

            u64 macc[16];
#pragma unroll
            for (int p = 0; p < 16; p++) macc[p] = 0ull;

            const float* wp = whT + tid;
#pragma unroll 4
            for (int k = 0; k < HID; k++) {
                u64 wd = dup2(wp[(size_t)k * 512]);
                const ulonglong2* hp = (const ulonglong2*)(h_s + k * HS_STR);
                ulonglong2 H0 = hp[0], H1 = hp[1], H2 = hp[2], H3 = hp[3];
                ulonglong2 H4 = hp[4], H5 = hp[5], H6 = hp[6], H7 = hp[7];
                fma2(macc[0], wd, H0.x);  fma2(macc[1], wd, H0.y);
                fma2(macc[2], wd, H1.x);  fma2(macc[3], wd, H1.y);
                fma2(macc[4], wd, H2.x);  fma2(macc[5], wd, H2.y);
                fma2(macc[6], wd, H3.x);  fma2(macc[7], wd, H3.y);
                fma2(macc[8], wd, H4.x);  fma2(macc[9], wd, H4.y);
                fma2(macc[10], wd, H5.x); fma2(macc[11], wd, H5.y);
                fma2(macc[12], wd, H6.x); fma2(macc[13], wd, H6.y);
                fma2(macc[14], wd, H7.x); fma2(macc[15], wd, H7.y);
            }
            const float* ms = &msall[t * 32];
#pragma unroll
            for (int p = 0; p < 16; p++) {
                u64 mp = pack2(ms[2 * p], ms[2 * p + 1]);
                *(u64*)&gs[tid * GS_STR + 2 * p] = fma2o(macc[p], mp, gxp[p]);
            }
        }
        __syncthreads();

        // ---- update ----
#pragma unroll
        for (int i = 0; i < 8; i++) {
            int e = tid + i * 512;
            int k = e >> 5, r = e & 31;
            float m = msall[t * 32 + r];
            float ig = gs[k * GS_STR + r];
            float fg = gs[(HID + k) * GS_STR + r];
            float gg = gs[(2 * HID + k) * GS_STR + r];
            float og = gs[(3 * HID + k) * GS_STR + r];
            float c = fsig(fg) * (creg[i] * m) + fsig(ig) * ftanh(gg);
            creg[i] = c;
            h_s[k * HS_STR + r] = fsig(og) * ftanh(c);
        }
        __syncthreads();
    }

    // ---- final heads (t = T_LEN-1) ----
    if (tid < LROWS * 7) {
        float s = bsh[c_h];
#pragma unroll 8
        for (int k = 0; k < HID; k++)
            s += h_s[k * HS_STR + r_h] * whead[k * 8 + c_h];
        out[((size_t)(T_LEN - 1) * B_ENV + r0) * 7 + tid] = s;
    }
}

// ---------------------------------------------------------------------------
// Launch
// ---------------------------------------------------------------------------
extern "C" void kernel_launch(void* const* d_in, const int* in_sizes, int n_in,
                              void* d_out, int out_size)
{
    const float* image = (const float*)d_in[0];
    const float* location = (const float*)d_in[1];
    const float* energy = (const float*)d_in[2];
    const int*   done  = (const int*)d_in[3];
    const float* h0 = (const float*)d_in[4];
    const float* c0 = (const float*)d_in[5];
    const float* W1 = (const float*)d_in[6];
    const float* b1 = (const float*)d_in[7];
    const float* W2 = (const float*)d_in[8];
    const float* b2 = (const float*)d_in[9];
    const float* W3 = (const float*)d_in[10];
    const float* b3 = (const float*)d_in[11];
    const float* W4 = (const float*)d_in[12];
    const float* b4 = (const float*)d_in[13];
    const float* Wl = (const float*)d_in[14];
    const float* bl = (const float*)d_in[15];
    const float* We = (const float*)d_in[16];
    const float* be = (const float*)d_in[17];
    const float* Wih = (const float*)d_in[18];
    const float* Whh = (const float*)d_in[19];
    const float* bih = (const float*)d_in[20];
    const float* bhh = (const float*)d_in[21];
    const float* Wa = (const float*)d_in[22];
    const float* ba = (const float*)d_in[23];
    const float* Wc = (const float*)d_in[24];
    const float* bc = (const float*)d_in[25];
    float* out = (float*)d_out;

    __half* pgxh;
    float *pwg, *pbg, *pwhT;
    cudaGetSymbolAddress((void**)&pgxh, g_gxh);
    cudaGetSymbolAddress((void**)&pwg, g_wg);
    cudaGetSymbolAddress((void**)&pbg, g_bg);
    cudaGetSymbolAddress((void**)&pwhT, g_whT);

    prep_wg<<<(36 * 512 + 255) / 256, 256>>>(Wih, Wl, We, pwg);
    prep_bg<<<2, 256>>>(Wih, bl, be, bih, bhh, pbg);
    prep_whT<<<(HID * 512 + 255) / 256, 256>>>(Whh, pwhT);

    const int smemM = (256 * SS + 36 * SS + 32 * 264) * 4;   // 187,968 B
    const int smemL = (HID * HS_STR + 512 * GS_STR + T_LEN * 32 + HID * 8 + 8) * 4;
    cudaFuncSetAttribute(mega_enc, cudaFuncAttributeMaxDynamicSharedMemorySize, smemM);
    cudaFuncSetAttribute(lstm_v7, cudaFuncAttributeMaxDynamicSharedMemorySize, smemL);

    mega_enc<<<N_TOT / 128, 512, smemM>>>(image, location, energy,
                                          W1, b1, W2, b2, W3, b3, W4, b4,
                                          pwg, pbg, pgxh);
    lstm_v7<<<B_ENV / LROWS, 512, smemL>>>(pgxh, done, h0, c0, pwhT,
                                           Wa, ba, Wc, bc, out);
}

// round 14
// speedup vs baseline: 1.5977x; 1.5977x over previous
#include <cuda_runtime.h>
#include <math.h>
#include <stdint.h>

// Problem constants (fixed by the reference)
#define T_LEN 128
#define B_ENV 4096
#define N_TOT (T_LEN * B_ENV)   // 524288
#define HID   128
#define NA    6

// ---------------------------------------------------------------------------
// Scratch (device globals — no runtime allocation allowed)
// ---------------------------------------------------------------------------
__device__ float g_gx[(size_t)N_TOT * 512];   // 1 GB  precomputed x-gates (fp32)
__device__ float g_wg[36 * 512];              // combined gx weight, k-major
__device__ float g_bg[512];                   // combined gate bias
__device__ float g_whT[HID * 512];            // Whh transposed: [k][j]

// ---------------------------------------------------------------------------
// Packed f32x2 helpers
// ---------------------------------------------------------------------------
typedef unsigned long long u64;
__device__ __forceinline__ u64 pack2(float lo, float hi) {
    u64 r; asm("mov.b64 %0, {%1, %2};" : "=l"(r) : "f"(lo), "f"(hi)); return r;
}
__device__ __forceinline__ u64 dup2(float x) {
    u64 r; asm("mov.b64 %0, {%1, %1};" : "=l"(r) : "f"(x)); return r;
}
__device__ __forceinline__ void fma2(u64& acc, u64 a, u64 b) {
    asm("fma.rn.f32x2 %0, %1, %2, %0;" : "+l"(acc) : "l"(a), "l"(b));
}
__device__ __forceinline__ u64 fma2o(u64 a, u64 b, u64 c) {
    u64 r; asm("fma.rn.f32x2 %0, %1, %2, %3;" : "=l"(r) : "l"(a), "l"(b), "l"(c));
    return r;
}
__device__ __forceinline__ void unpack2(u64 v, float& lo, float& hi) {
    asm("mov.b64 {%0, %1}, %2;" : "=f"(lo), "=f"(hi) : "l"(v));
}
// Hardware tanh (MUFU.TANH, sm_75+ base ISA)
__device__ __forceinline__ float ftanh(float x) {
    float y; asm("tanh.approx.f32 %0, %1;" : "=f"(y) : "f"(x)); return y;
}
__device__ __forceinline__ float fsig(float x) {
    return fmaf(0.5f, ftanh(0.5f * x), 0.5f);
}

// ---------------------------------------------------------------------------
// Weight prep
// ---------------------------------------------------------------------------
__global__ void prep_wg(const float* __restrict__ Wih, const float* __restrict__ Wl,
                        const float* __restrict__ We, float* __restrict__ out)
{
    int idx = blockIdx.x * 256 + threadIdx.x;
    if (idx >= 36 * 512) return;
    int k = idx >> 9, n = idx & 511;
    float v = 0.f;
    if (k < 32) {
        v = Wih[n * 96 + k];
    } else if (k < 34) {
        int d = k - 32;
        float s = 0.f;
        for (int j = 0; j < 32; j++) s += Wl[d * 32 + j] * Wih[n * 96 + 32 + j];
        v = s * 0.1f;
    } else if (k == 34) {
        float s = 0.f;
        for (int j = 0; j < 32; j++) s += We[j] * Wih[n * 96 + 64 + j];
        v = s * (1.f / 200.f);
    }
    out[k * 512 + n] = v;
}

__global__ void prep_bg(const float* __restrict__ Wih, const float* __restrict__ bl,
                        const float* __restrict__ be, const float* __restrict__ bih,
                        const float* __restrict__ bhh, float* __restrict__ bg)
{
    int n = blockIdx.x * 256 + threadIdx.x;
    if (n >= 512) return;
    float s = bih[n] + bhh[n];
    for (int j = 0; j < 32; j++)
        s += bl[j] * Wih[n * 96 + 32 + j] + be[j] * Wih[n * 96 + 64 + j];
    bg[n] = s;
}

__global__ void prep_whT(const float* __restrict__ Whh, float* __restrict__ whT)
{
    int idx = blockIdx.x * 256 + threadIdx.x;
    if (idx >= HID * 512) return;
    int k = idx >> 9, j = idx & 511;
    whT[idx] = Whh[j * HID + k];
}

// ---------------------------------------------------------------------------
// MEGA encoder: image -> f1 -> f2 -> f3 -> f4(+loc/eng) -> gx (fp32), ONE kernel.
// (Identical to the R12 5459us version.)
// ---------------------------------------------------------------------------
#define SS 132

__global__ __launch_bounds__(512) void mega_enc(
    const float* __restrict__ img, const float* __restrict__ loc,
    const float* __restrict__ eng,
    const float* __restrict__ W1, const float* __restrict__ b1,
    const float* __restrict__ W2, const float* __restrict__ b2,
    const float* __restrict__ W3, const float* __restrict__ b3,
    const float* __restrict__ W4, const float* __restrict__ b4,
    const float* __restrict__ wg, const float* __restrict__ bg,
    float* __restrict__ gx)
{
    extern __shared__ float sm[];
    float* fA   = sm;                    // [256][SS]
    float* faux = fA + 256 * SS;         // [36][SS]
    float* bs   = faux + 36 * SS;        // [32][264]

    const int tid = threadIdx.x;
    const int rowBase = blockIdx.x * 128;

    for (int i = tid; i < 128 * 25; i += 512) {
        int k = i % 25, m = i / 25;
        faux[k * SS + m] = img[(size_t)(rowBase + m) * 25 + k] * (1.f / 255.f);
    }
    for (int i = tid; i < 25 * 256; i += 512) {
        int k = i >> 8, n = i & 255;
        bs[k * 264 + n] = W1[i];
    }
    __syncthreads();

    // ================= phase 1: f1 = relu(x @ W1 + b1), K=25 =================
    {
        const int rg = tid >> 6;
        const int cg = tid & 63;
        u64 acc[8][4];
#pragma unroll
        for (int p = 0; p < 8; p++)
#pragma unroll
            for (int j = 0; j < 4; j++) acc[p][j] = 0ull;

        for (int k = 0; k < 25; k++) {
            const ulonglong2* ap = (const ulonglong2*)(faux + k * SS + rg * 16);
            ulonglong2 A0 = ap[0], A1 = ap[1], A2 = ap[2], A3 = ap[3];
            u64 av[8] = {A0.x, A0.y, A1.x, A1.y, A2.x, A2.y, A3.x, A3.y};
            float4 q = *(const float4*)(bs + k * 264 + cg * 4);
            float bv[4] = {q.x, q.y, q.z, q.w};
#pragma unroll
            for (int j = 0; j < 4; j++) {
                u64 bd = dup2(bv[j]);
#pragma unroll
                for (int p = 0; p < 8; p++) fma2(acc[p][j], av[p], bd);
            }
        }
        float4 c1 = *(const float4*)(b1 + cg * 4);
        float bias1[4] = {c1.x, c1.y, c1.z, c1.w};
        __syncthreads();
#pragma unroll
        for (int p = 0; p < 8; p++) {
            int m0 = rg * 16 + 2 * p;
#pragma unroll
            for (int j = 0; j < 4; j++) {
                float o0, o1;
                unpack2(acc[p][j], o0, o1);
                o0 = fmaxf(o0 + bias1[j], 0.f);
                o1 = fmaxf(o1 + bias1[j], 0.f);
                *(u64*)&fA[(cg * 4 + j) * SS + m0] = pack2(o0, o1);
            }
        }
    }

    // ================= phase 2: f2 = relu(f1 @ W2 + b2), K=256 ================
    {
        const int rg = tid >> 6;
        const int cg = tid & 63;
        float ldr[8];
#define LOADW2(c)                                                      \
    _Pragma("unroll") for (int i = 0; i < 8; i++) {                    \
        int idx = tid + i * 512;                                       \
        int k = idx >> 8, n = idx & 255;                               \
        ldr[i] = W2[(size_t)((c) * 16 + k) * 256 + n];                 \
    }
#define STW2(buf)                                                      \
    _Pragma("unroll") for (int i = 0; i < 8; i++) {                    \
        int idx = tid + i * 512;                                       \
        int k = idx >> 8, n = idx & 255;                               \
        bs[((buf) * 16 + k) * 264 + n] = ldr[i];                       \
    }
        LOADW2(0);
        __syncthreads();
        STW2(0);
        __syncthreads();

        u64 acc[8][4];
#pragma unroll
        for (int p = 0; p < 8; p++)
#pragma unroll
            for (int j = 0; j < 4; j++) acc[p][j] = 0ull;

        for (int c = 0; c < 16; c++) {
            if (c < 15) { LOADW2(c + 1); }
            const float* bsc = bs + (c & 1) * 16 * 264;
            const float* f1c = fA + c * 16 * SS;
#pragma unroll
            for (int k = 0; k < 16; k++) {
                const ulonglong2* ap = (const ulonglong2*)(f1c + k * SS + rg * 16);
                ulonglong2 A0 = ap[0], A1 = ap[1], A2 = ap[2], A3 = ap[3];
                u64 av[8] = {A0.x, A0.y, A1.x, A1.y, A2.x, A2.y, A3.x, A3.y};
                float4 q = *(const float4*)(bsc + k * 264 + cg * 4);
                float bv[4] = {q.x, q.y, q.z, q.w};
#pragma unroll
                for (int j = 0; j < 4; j++) {
                    u64 bd = dup2(bv[j]);
#pragma unroll
                    for (int p = 0; p < 8; p++) fma2(acc[p][j], av[p], bd);
                }
            }
            if (c < 15) { STW2((c + 1) & 1); }
            __syncthreads();
        }
#undef LOADW2
#undef STW2
        float4 c2 = *(const float4*)(b2 + cg * 4);
        float bias2[4] = {c2.x, c2.y, c2.z, c2.w};
#pragma unroll
        for (int p = 0; p < 8; p++) {
            int m0 = rg * 16 + 2 * p;
#pragma unroll
            for (int j = 0; j < 4; j++) {
                float o0, o1;
                unpack2(acc[p][j], o0, o1);
                o0 = fmaxf(o0 + bias2[j], 0.f);
                o1 = fmaxf(o1 + bias2[j], 0.f);
                *(u64*)&fA[(cg * 4 + j) * SS + m0] = pack2(o0, o1);
            }
        }
    }
    __syncthreads();

    // ================= phase 3: f3 = relu(f2 @ W3 + b3), K=256 ================
    {
        const int rg = tid >> 5;
        const int cg = tid & 31;
        float ldr[4];
#define LOADW3(c)                                                      \
    _Pragma("unroll") for (int i = 0; i < 4; i++) {                    \
        int idx = tid + i * 512;                                       \
        int k = idx >> 7, n = idx & 127;                               \
        ldr[i] = W3[(size_t)((c) * 16 + k) * 128 + n];                 \
    }
#define STW3(buf)                                                      \
    _Pragma("unroll") for (int i = 0; i < 4; i++) {                    \
        int idx = tid + i * 512;                                       \
        int k = idx >> 7, n = idx & 127;                               \
        bs[((buf) * 16 + k) * 132 + n] = ldr[i];                       \
    }
        LOADW3(0);
        STW3(0);
        __syncthreads();

        u64 acc[4][4];
#pragma unroll
        for (int p = 0; p < 4; p++)
#pragma unroll
            for (int j = 0; j < 4; j++) acc[p][j] = 0ull;

        for (int c = 0; c < 16; c++) {
            if (c < 15) { LOADW3(c + 1); }
            const float* bsc = bs + (c & 1) * 16 * 132;
            const float* f2c = fA + c * 16 * SS;
#pragma unroll
            for (int k = 0; k < 16; k++) {
                const ulonglong2* ap = (const ulonglong2*)(f2c + k * SS + rg * 8);
                ulonglong2 A0 = ap[0], A1 = ap[1];
                u64 av[4] = {A0.x, A0.y, A1.x, A1.y};
                float4 q = *(const float4*)(bsc + k * 132 + cg * 4);
                float bv[4] = {q.x, q.y, q.z, q.w};
#pragma unroll
                for (int j = 0; j < 4; j++) {
                    u64 bd = dup2(bv[j]);
#pragma unroll
                    for (int p = 0; p < 4; p++) fma2(acc[p][j], av[p], bd);
                }
            }
            if (c < 15) { STW3((c + 1) & 1); }
            __syncthreads();
        }
#undef LOADW3
#undef STW3
        float4 cb = *(const float4*)(b3 + cg * 4);
        float bias3[4] = {cb.x, cb.y, cb.z, cb.w};
#pragma unroll
        for (int p = 0; p < 4; p++) {
            int m0 = rg * 8 + 2 * p;
#pragma unroll
            for (int j = 0; j < 4; j++) {
                float o0, o1;
                unpack2(acc[p][j], o0, o1);
                o0 = fmaxf(o0 + bias3[j], 0.f);
                o1 = fmaxf(o1 + bias3[j], 0.f);
                *(u64*)&fA[(cg * 4 + j) * SS + m0] = pack2(o0, o1);
            }
        }
    }
    __syncthreads();

    // ================= phase 4: f4 = relu(f3 @ W4 + b4), K=128 ================
    {
        const int tr4 = tid >> 3;
        const int tc4 = tid & 7;
        u64 acc[4] = {0ull, 0ull, 0ull, 0ull};
#pragma unroll 4
        for (int k = 0; k < 128; k++) {
            u64 a = *(const u64*)&fA[k * SS + tr4 * 2];
            float4 q = *(const float4*)&W4[k * 32 + tc4 * 4];
            float bv[4] = {q.x, q.y, q.z, q.w};
#pragma unroll
            for (int j = 0; j < 4; j++) fma2(acc[j], a, dup2(bv[j]));
        }
        float4 cb = *(const float4*)(b4 + tc4 * 4);
        float bias4[4] = {cb.x, cb.y, cb.z, cb.w};
        __syncthreads();
#pragma unroll
        for (int j = 0; j < 4; j++) {
            float o0, o1;
            unpack2(acc[j], o0, o1);
            o0 = fmaxf(o0 + bias4[j], 0.f);
            o1 = fmaxf(o1 + bias4[j], 0.f);
            *(u64*)&faux[(tc4 * 4 + j) * SS + tr4 * 2] = pack2(o0, o1);
        }
        if (tid < 128) {
            int n = rowBase + tid;
            faux[32 * SS + tid] = loc[2 * n];
            faux[33 * SS + tid] = loc[2 * n + 1];
            faux[34 * SS + tid] = eng[n];
            faux[35 * SS + tid] = 0.f;
        }
    }
    __syncthreads();

    // ================= phase gx: gates = f4e @ Wg + bg, K=36 ==================
    {
        const int rg = tid >> 6;
        const int cg = tid & 63;
        for (int pc = 0; pc < 2; pc++) {
            u64 acc[8][4];
#pragma unroll
            for (int p = 0; p < 8; p++)
#pragma unroll
                for (int j = 0; j < 4; j++) acc[p][j] = 0ull;

#pragma unroll 4
            for (int k = 0; k < 36; k++) {
                const ulonglong2* ap = (const ulonglong2*)(faux + k * SS + rg * 16);
                ulonglong2 A0 = ap[0], A1 = ap[1], A2 = ap[2], A3 = ap[3];
                u64 av[8] = {A0.x, A0.y, A1.x, A1.y, A2.x, A2.y, A3.x, A3.y};
                float4 q = *(const float4*)&wg[k * 512 + pc * 256 + cg * 4];
                float bv[4] = {q.x, q.y, q.z, q.w};
#pragma unroll
                for (int j = 0; j < 4; j++) {
                    u64 bd = dup2(bv[j]);
#pragma unroll
                    for (int p = 0; p < 8; p++) fma2(acc[p][j], av[p], bd);
                }
            }
            float4 cb = *(const float4*)(bg + pc * 256 + cg * 4);
            float bias0[4] = {cb.x, cb.y, cb.z, cb.w};
#pragma unroll
            for (int p = 0; p < 8; p++) {
                int m0 = rowBase + rg * 16 + 2 * p;
                float o0[4], o1[4];
#pragma unroll
                for (int j = 0; j < 4; j++) {
                    unpack2(acc[p][j], o0[j], o1[j]);
                    o0[j] += bias0[j];
                    o1[j] += bias0[j];
                }
                *(float4*)&gx[(size_t)m0 * 512 + pc * 256 + cg * 4] =
                    make_float4(o0[0], o0[1], o0[2], o0[3]);
                *(float4*)&gx[(size_t)(m0 + 1) * 512 + pc * 256 + cg * 4] =
                    make_float4(o1[0], o1[1], o1[2], o1[3]);
            }
        }
    }
}

// ---------------------------------------------------------------------------
// LSTM v8: 32 rows/CTA (128 CTAs, 1/SM), coalesced WhhT, fp32 gx prefetch,
// HW-tanh, 2 barriers/step, heads fused (warps 0-6, reads h_s only).
// ---------------------------------------------------------------------------
#define LROWS 32
#define HS_STR 36
#define GS_STR 34

__global__ __launch_bounds__(512) void lstm_v8(
    const float* __restrict__ gx, const int* __restrict__ done,
    const float* __restrict__ h0, const float* __restrict__ c0,
    const float* __restrict__ whT,
    const float* __restrict__ Wa, const float* __restrict__ ba,
    const float* __restrict__ Wc, const float* __restrict__ bc,
    float* __restrict__ out)
{
    extern __shared__ float sm[];
    float* h_s = sm;                        // [HID][HS_STR]
    float* gs  = h_s + HID * HS_STR;        // [512][GS_STR]
    float* msall = gs + 512 * GS_STR;       // [T_LEN*32]
    float* whead = msall + T_LEN * 32;      // [HID*8]
    float* bsh   = whead + HID * 8;         // [8]

    const int tid = threadIdx.x;
    const int r0 = blockIdx.x * LROWS;
    const int r_h = tid / 7;                // head row (valid for tid<224)
    const int c_h = tid - r_h * 7;          // head col

    float creg[8];
#pragma unroll
    for (int i = 0; i < 8; i++) {
        int e = tid + i * 512;
        int k = e >> 5, r = e & 31;
        h_s[k * HS_STR + r] = h0[(r0 + r) * HID + k];
        creg[i] = c0[(r0 + r) * HID + k];
    }
#pragma unroll
    for (int i = 0; i < 8; i++) {
        int e = tid + i * 512;
        int t = e >> 5, r = e & 31;
        msall[e] = done[t * B_ENV + r0 + r] ? 0.f : 1.f;
    }
    for (int i = tid; i < HID * 8; i += 512) {
        int k = i >> 3, c = i & 7;
        float v = 0.f;
        if (c < NA) v = Wa[k * NA + c];
        else if (c == NA) v = Wc[k];
        whead[i] = v;
    }
    if (tid < 8) bsh[tid] = (tid < NA) ? ba[tid] : ((tid == NA) ? bc[0] : 0.f);
    __syncthreads();

    for (int t = 0; t < T_LEN; t++) {
        // ---- gx prefetch (fp32, latency hidden under matvec) ----
        const float* gp = gx + ((size_t)t * B_ENV + r0) * 512 + tid;
        u64 gxp[16];
#pragma unroll
        for (int p = 0; p < 16; p++)
            gxp[p] = pack2(gp[(size_t)(2 * p) * 512], gp[(size_t)(2 * p + 1) * 512]);

        // ---- heads(t-1): warps 0-6 (224 threads), reads h_s only ----
        if (t > 0 && tid < LROWS * 7) {
            float s = bsh[c_h];
#pragma unroll 8
            for (int k = 0; k < HID; k++)
                s += h_s[k * HS_STR + r_h] * whead[k * 8 + c_h];
            out[((size_t)(t - 1) * B_ENV + r0) * 7 + tid] = s;
        }

        // ---- gates: thread j = tid computes gates[*, j] for 32 rows ----
        {
            u64 macc[16];
#pragma unroll
            for (int p = 0; p < 16; p++) macc[p] = 0ull;

            const float* wp = whT + tid;
#pragma unroll 4
            for (int k = 0; k < HID; k++) {
                u64 wd = dup2(wp[(size_t)k * 512]);
                const ulonglong2* hp = (const ulonglong2*)(h_s + k * HS_STR);
                ulonglong2 H0 = hp[0], H1 = hp[1], H2 = hp[2], H3 = hp[3];
                ulonglong2 H4 = hp[4], H5 = hp[5], H6 = hp[6], H7 = hp[7];
                fma2(macc[0], wd, H0.x);  fma2(macc[1], wd, H0.y);
                fma2(macc[2], wd, H1.x);  fma2(macc[3], wd, H1.y);
                fma2(macc[4], wd, H2.x);  fma2(macc[5], wd, H2.y);
                fma2(macc[6], wd, H3.x);  fma2(macc[7], wd, H3.y);
                fma2(macc[8], wd, H4.x);  fma2(macc[9], wd, H4.y);
                fma2(macc[10], wd, H5.x); fma2(macc[11], wd, H5.y);
                fma2(macc[12], wd, H6.x); fma2(macc[13], wd, H6.y);
                fma2(macc[14], wd, H7.x); fma2(macc[15], wd, H7.y);
            }
            const float* ms = &msall[t * 32];
#pragma unroll
            for (int p = 0; p < 16; p++) {
                u64 mp = pack2(ms[2 * p], ms[2 * p + 1]);
                *(u64*)&gs[tid * GS_STR + 2 * p] = fma2o(macc[p], mp, gxp[p]);
            }
        }
        __syncthreads();

        // ---- update ----
#pragma unroll
        for (int i = 0; i < 8; i++) {
            int e = tid + i * 512;
            int k = e >> 5, r = e & 31;
            float m = msall[t * 32 + r];
            float ig = gs[k * GS_STR + r];
            float fg = gs[(HID + k) * GS_STR + r];
            float gg = gs[(2 * HID + k) * GS_STR + r];
            float og = gs[(3 * HID + k) * GS_STR + r];
            float c = fsig(fg) * (creg[i] * m) + fsig(ig) * ftanh(gg);
            creg[i] = c;
            h_s[k * HS_STR + r] = fsig(og) * ftanh(c);
        }
        __syncthreads();
    }

    // ---- final heads (t = T_LEN-1) ----
    if (tid < LROWS * 7) {
        float s = bsh[c_h];
#pragma unroll 8
        for (int k = 0; k < HID; k++)
            s += h_s[k * HS_STR + r_h] * whead[k * 8 + c_h];
        out[((size_t)(T_LEN - 1) * B_ENV + r0) * 7 + tid] = s;
    }
}

// ---------------------------------------------------------------------------
// Launch
// ---------------------------------------------------------------------------
extern "C" void kernel_launch(void* const* d_in, const int* in_sizes, int n_in,
                              void* d_out, int out_size)
{
    const float* image = (const float*)d_in[0];
    const float* location = (const float*)d_in[1];
    const float* energy = (const float*)d_in[2];
    const int*   done  = (const int*)d_in[3];
    const float* h0 = (const float*)d_in[4];
    const float* c0 = (const float*)d_in[5];
    const float* W1 = (const float*)d_in[6];
    const float* b1 = (const float*)d_in[7];
    const float* W2 = (const float*)d_in[8];
    const float* b2 = (const float*)d_in[9];
    const float* W3 = (const float*)d_in[10];
    const float* b3 = (const float*)d_in[11];
    const float* W4 = (const float*)d_in[12];
    const float* b4 = (const float*)d_in[13];
    const float* Wl = (const float*)d_in[14];
    const float* bl = (const float*)d_in[15];
    const float* We = (const float*)d_in[16];
    const float* be = (const float*)d_in[17];
    const float* Wih = (const float*)d_in[18];
    const float* Whh = (const float*)d_in[19];
    const float* bih = (const float*)d_in[20];
    const float* bhh = (const float*)d_in[21];
    const float* Wa = (const float*)d_in[22];
    const float* ba = (const float*)d_in[23];
    const float* Wc = (const float*)d_in[24];
    const float* bc = (const float*)d_in[25];
    float* out = (float*)d_out;

    float *pgx, *pwg, *pbg, *pwhT;
    cudaGetSymbolAddress((void**)&pgx, g_gx);
    cudaGetSymbolAddress((void**)&pwg, g_wg);
    cudaGetSymbolAddress((void**)&pbg, g_bg);
    cudaGetSymbolAddress((void**)&pwhT, g_whT);

    prep_wg<<<(36 * 512 + 255) / 256, 256>>>(Wih, Wl, We, pwg);
    prep_bg<<<2, 256>>>(Wih, bl, be, bih, bhh, pbg);
    prep_whT<<<(HID * 512 + 255) / 256, 256>>>(Whh, pwhT);

    const int smemM = (256 * SS + 36 * SS + 32 * 264) * 4;   // 187,968 B
    const int smemL = (HID * HS_STR + 512 * GS_STR + T_LEN * 32 + HID * 8 + 8) * 4;
    cudaFuncSetAttribute(mega_enc, cudaFuncAttributeMaxDynamicSharedMemorySize, smemM);
    cudaFuncSetAttribute(lstm_v8, cudaFuncAttributeMaxDynamicSharedMemorySize, smemL);

    mega_enc<<<N_TOT / 128, 512, smemM>>>(image, location, energy,
                                          W1, b1, W2, b2, W3, b3, W4, b4,
                                          pwg, pbg, pgx);
    lstm_v8<<<B_ENV / LROWS, 512, smemL>>>(pgx, done, h0, c0, pwhT,
                                           Wa, ba, Wc, bc, out);
}

// round 15
// speedup vs baseline: 1.6051x; 1.0046x over previous
#include <cuda_runtime.h>
#include <math.h>
#include <stdint.h>

// Problem constants (fixed by the reference)
#define T_LEN 128
#define B_ENV 4096
#define N_TOT (T_LEN * B_ENV)   // 524288
#define HID   128
#define NA    6

// ---------------------------------------------------------------------------
// Scratch (device globals — no runtime allocation allowed)
// ---------------------------------------------------------------------------
__device__ float g_gx[(size_t)N_TOT * 512];   // 1 GB  precomputed x-gates (fp32)
__device__ float g_wg[36 * 512];              // combined gx weight, k-major
__device__ float g_bg[512];                   // combined gate bias
__device__ float g_whT[HID * 512];            // Whh transposed: [k][j]

// ---------------------------------------------------------------------------
// Packed f32x2 helpers
// ---------------------------------------------------------------------------
typedef unsigned long long u64;
__device__ __forceinline__ u64 pack2(float lo, float hi) {
    u64 r; asm("mov.b64 %0, {%1, %2};" : "=l"(r) : "f"(lo), "f"(hi)); return r;
}
__device__ __forceinline__ u64 dup2(float x) {
    u64 r; asm("mov.b64 %0, {%1, %1};" : "=l"(r) : "f"(x)); return r;
}
__device__ __forceinline__ void fma2(u64& acc, u64 a, u64 b) {
    asm("fma.rn.f32x2 %0, %1, %2, %0;" : "+l"(acc) : "l"(a), "l"(b));
}
__device__ __forceinline__ u64 fma2o(u64 a, u64 b, u64 c) {
    u64 r; asm("fma.rn.f32x2 %0, %1, %2, %3;" : "=l"(r) : "l"(a), "l"(b), "l"(c));
    return r;
}
__device__ __forceinline__ void unpack2(u64 v, float& lo, float& hi) {
    asm("mov.b64 {%0, %1}, %2;" : "=f"(lo), "=f"(hi) : "l"(v));
}
// Hardware tanh (MUFU.TANH, sm_75+ base ISA)
__device__ __forceinline__ float ftanh(float x) {
    float y; asm("tanh.approx.f32 %0, %1;" : "=f"(y) : "f"(x)); return y;
}
__device__ __forceinline__ float fsig(float x) {
    return fmaf(0.5f, ftanh(0.5f * x), 0.5f);
}

// ---------------------------------------------------------------------------
// Weight prep
// ---------------------------------------------------------------------------
__global__ void prep_wg(const float* __restrict__ Wih, const float* __restrict__ Wl,
                        const float* __restrict__ We, float* __restrict__ out)
{
    int idx = blockIdx.x * 256 + threadIdx.x;
    if (idx >= 36 * 512) return;
    int k = idx >> 9, n = idx & 511;
    float v = 0.f;
    if (k < 32) {
        v = Wih[n * 96 + k];
    } else if (k < 34) {
        int d = k - 32;
        float s = 0.f;
        for (int j = 0; j < 32; j++) s += Wl[d * 32 + j] * Wih[n * 96 + 32 + j];
        v = s * 0.1f;
    } else if (k == 34) {
        float s = 0.f;
        for (int j = 0; j < 32; j++) s += We[j] * Wih[n * 96 + 64 + j];
        v = s * (1.f / 200.f);
    }
    out[k * 512 + n] = v;
}

__global__ void prep_bg(const float* __restrict__ Wih, const float* __restrict__ bl,
                        const float* __restrict__ be, const float* __restrict__ bih,
                        const float* __restrict__ bhh, float* __restrict__ bg)
{
    int n = blockIdx.x * 256 + threadIdx.x;
    if (n >= 512) return;
    float s = bih[n] + bhh[n];
    for (int j = 0; j < 32; j++)
        s += bl[j] * Wih[n * 96 + 32 + j] + be[j] * Wih[n * 96 + 64 + j];
    bg[n] = s;
}

__global__ void prep_whT(const float* __restrict__ Whh, float* __restrict__ whT)
{
    int idx = blockIdx.x * 256 + threadIdx.x;
    if (idx >= HID * 512) return;
    int k = idx >> 9, j = idx & 511;
    whT[idx] = Whh[j * HID + k];
}

// ---------------------------------------------------------------------------
// MEGA encoder (unchanged from 5459us best)
// ---------------------------------------------------------------------------
#define SS 132

__global__ __launch_bounds__(512) void mega_enc(
    const float* __restrict__ img, const float* __restrict__ loc,
    const float* __restrict__ eng,
    const float* __restrict__ W1, const float* __restrict__ b1,
    const float* __restrict__ W2, const float* __restrict__ b2,
    const float* __restrict__ W3, const float* __restrict__ b3,
    const float* __restrict__ W4, const float* __restrict__ b4,
    const float* __restrict__ wg, const float* __restrict__ bg,
    float* __restrict__ gx)
{
    extern __shared__ float sm[];
    float* fA   = sm;                    // [256][SS]
    float* faux = fA + 256 * SS;         // [36][SS]
    float* bs   = faux + 36 * SS;        // [32][264]

    const int tid = threadIdx.x;
    const int rowBase = blockIdx.x * 128;

    for (int i = tid; i < 128 * 25; i += 512) {
        int k = i % 25, m = i / 25;
        faux[k * SS + m] = img[(size_t)(rowBase + m) * 25 + k] * (1.f / 255.f);
    }
    for (int i = tid; i < 25 * 256; i += 512) {
        int k = i >> 8, n = i & 255;
        bs[k * 264 + n] = W1[i];
    }
    __syncthreads();

    // ================= phase 1: f1 = relu(x @ W1 + b1), K=25 =================
    {
        const int rg = tid >> 6;
        const int cg = tid & 63;
        u64 acc[8][4];
#pragma unroll
        for (int p = 0; p < 8; p++)
#pragma unroll
            for (int j = 0; j < 4; j++) acc[p][j] = 0ull;

        for (int k = 0; k < 25; k++) {
            const ulonglong2* ap = (const ulonglong2*)(faux + k * SS + rg * 16);
            ulonglong2 A0 = ap[0], A1 = ap[1], A2 = ap[2], A3 = ap[3];
            u64 av[8] = {A0.x, A0.y, A1.x, A1.y, A2.x, A2.y, A3.x, A3.y};
            float4 q = *(const float4*)(bs + k * 264 + cg * 4);
            float bv[4] = {q.x, q.y, q.z, q.w};
#pragma unroll
            for (int j = 0; j < 4; j++) {
                u64 bd = dup2(bv[j]);
#pragma unroll
                for (int p = 0; p < 8; p++) fma2(acc[p][j], av[p], bd);
            }
        }
        float4 c1 = *(const float4*)(b1 + cg * 4);
        float bias1[4] = {c1.x, c1.y, c1.z, c1.w};
        __syncthreads();
#pragma unroll
        for (int p = 0; p < 8; p++) {
            int m0 = rg * 16 + 2 * p;
#pragma unroll
            for (int j = 0; j < 4; j++) {
                float o0, o1;
                unpack2(acc[p][j], o0, o1);
                o0 = fmaxf(o0 + bias1[j], 0.f);
                o1 = fmaxf(o1 + bias1[j], 0.f);
                *(u64*)&fA[(cg * 4 + j) * SS + m0] = pack2(o0, o1);
            }
        }
    }

    // ================= phase 2: f2 = relu(f1 @ W2 + b2), K=256 ================
    {
        const int rg = tid >> 6;
        const int cg = tid & 63;
        float ldr[8];
#define LOADW2(c)                                                      \
    _Pragma("unroll") for (int i = 0; i < 8; i++) {                    \
        int idx = tid + i * 512;                                       \
        int k = idx >> 8, n = idx & 255;                               \
        ldr[i] = W2[(size_t)((c) * 16 + k) * 256 + n];                 \
    }
#define STW2(buf)                                                      \
    _Pragma("unroll") for (int i = 0; i < 8; i++) {                    \
        int idx = tid + i * 512;                                       \
        int k = idx >> 8, n = idx & 255;                               \
        bs[((buf) * 16 + k) * 264 + n] = ldr[i];                       \
    }
        LOADW2(0);
        __syncthreads();
        STW2(0);
        __syncthreads();

        u64 acc[8][4];
#pragma unroll
        for (int p = 0; p < 8; p++)
#pragma unroll
            for (int j = 0; j < 4; j++) acc[p][j] = 0ull;

        for (int c = 0; c < 16; c++) {
            if (c < 15) { LOADW2(c + 1); }
            const float* bsc = bs + (c & 1) * 16 * 264;
            const float* f1c = fA + c * 16 * SS;
#pragma unroll
            for (int k = 0; k < 16; k++) {
                const ulonglong2* ap = (const ulonglong2*)(f1c + k * SS + rg * 16);
                ulonglong2 A0 = ap[0], A1 = ap[1], A2 = ap[2], A3 = ap[3];
                u64 av[8] = {A0.x, A0.y, A1.x, A1.y, A2.x, A2.y, A3.x, A3.y};
                float4 q = *(const float4*)(bsc + k * 264 + cg * 4);
                float bv[4] = {q.x, q.y, q.z, q.w};
#pragma unroll
                for (int j = 0; j < 4; j++) {
                    u64 bd = dup2(bv[j]);
#pragma unroll
                    for (int p = 0; p < 8; p++) fma2(acc[p][j], av[p], bd);
                }
            }
            if (c < 15) { STW2((c + 1) & 1); }
            __syncthreads();
        }
#undef LOADW2
#undef STW2
        float4 c2 = *(const float4*)(b2 + cg * 4);
        float bias2[4] = {c2.x, c2.y, c2.z, c2.w};
#pragma unroll
        for (int p = 0; p < 8; p++) {
            int m0 = rg * 16 + 2 * p;
#pragma unroll
            for (int j = 0; j < 4; j++) {
                float o0, o1;
                unpack2(acc[p][j], o0, o1);
                o0 = fmaxf(o0 + bias2[j], 0.f);
                o1 = fmaxf(o1 + bias2[j], 0.f);
                *(u64*)&fA[(cg * 4 + j) * SS + m0] = pack2(o0, o1);
            }
        }
    }
    __syncthreads();

    // ================= phase 3: f3 = relu(f2 @ W3 + b3), K=256 ================
    {
        const int rg = tid >> 5;
        const int cg = tid & 31;
        float ldr[4];
#define LOADW3(c)                                                      \
    _Pragma("unroll") for (int i = 0; i < 4; i++) {                    \
        int idx = tid + i * 512;                                       \
        int k = idx >> 7, n = idx & 127;                               \
        ldr[i] = W3[(size_t)((c) * 16 + k) * 128 + n];                 \
    }
#define STW3(buf)                                                      \
    _Pragma("unroll") for (int i = 0; i < 4; i++) {                    \
        int idx = tid + i * 512;                                       \
        int k = idx >> 7, n = idx & 127;                               \
        bs[((buf) * 16 + k) * 132 + n] = ldr[i];                       \
    }
        LOADW3(0);
        STW3(0);
        __syncthreads();

        u64 acc[4][4];
#pragma unroll
        for (int p = 0; p < 4; p++)
#pragma unroll
            for (int j = 0; j < 4; j++) acc[p][j] = 0ull;

        for (int c = 0; c < 16; c++) {
            if (c < 15) { LOADW3(c + 1); }
            const float* bsc = bs + (c & 1) * 16 * 132;
            const float* f2c = fA + c * 16 * SS;
#pragma unroll
            for (int k = 0; k < 16; k++) {
                const ulonglong2* ap = (const ulonglong2*)(f2c + k * SS + rg * 8);
                ulonglong2 A0 = ap[0], A1 = ap[1];
                u64 av[4] = {A0.x, A0.y, A1.x, A1.y};
                float4 q = *(const float4*)(bsc + k * 132 + cg * 4);
                float bv[4] = {q.x, q.y, q.z, q.w};
#pragma unroll
                for (int j = 0; j < 4; j++) {
                    u64 bd = dup2(bv[j]);
#pragma unroll
                    for (int p = 0; p < 4; p++) fma2(acc[p][j], av[p], bd);
                }
            }
            if (c < 15) { STW3((c + 1) & 1); }
            __syncthreads();
        }
#undef LOADW3
#undef STW3
        float4 cb = *(const float4*)(b3 + cg * 4);
        float bias3[4] = {cb.x, cb.y, cb.z, cb.w};
#pragma unroll
        for (int p = 0; p < 4; p++) {
            int m0 = rg * 8 + 2 * p;
#pragma unroll
            for (int j = 0; j < 4; j++) {
                float o0, o1;
                unpack2(acc[p][j], o0, o1);
                o0 = fmaxf(o0 + bias3[j], 0.f);
                o1 = fmaxf(o1 + bias3[j], 0.f);
                *(u64*)&fA[(cg * 4 + j) * SS + m0] = pack2(o0, o1);
            }
        }
    }
    __syncthreads();

    // ================= phase 4: f4 = relu(f3 @ W4 + b4), K=128 ================
    {
        const int tr4 = tid >> 3;
        const int tc4 = tid & 7;
        u64 acc[4] = {0ull, 0ull, 0ull, 0ull};
#pragma unroll 4
        for (int k = 0; k < 128; k++) {
            u64 a = *(const u64*)&fA[k * SS + tr4 * 2];
            float4 q = *(const float4*)&W4[k * 32 + tc4 * 4];
            float bv[4] = {q.x, q.y, q.z, q.w};
#pragma unroll
            for (int j = 0; j < 4; j++) fma2(acc[j], a, dup2(bv[j]));
        }
        float4 cb = *(const float4*)(b4 + tc4 * 4);
        float bias4[4] = {cb.x, cb.y, cb.z, cb.w};
        __syncthreads();
#pragma unroll
        for (int j = 0; j < 4; j++) {
            float o0, o1;
            unpack2(acc[j], o0, o1);
            o0 = fmaxf(o0 + bias4[j], 0.f);
            o1 = fmaxf(o1 + bias4[j], 0.f);
            *(u64*)&faux[(tc4 * 4 + j) * SS + tr4 * 2] = pack2(o0, o1);
        }
        if (tid < 128) {
            int n = rowBase + tid;
            faux[32 * SS + tid] = loc[2 * n];
            faux[33 * SS + tid] = loc[2 * n + 1];
            faux[34 * SS + tid] = eng[n];
            faux[35 * SS + tid] = 0.f;
        }
    }
    __syncthreads();

    // ================= phase gx: gates = f4e @ Wg + bg, K=36 ==================
    {
        const int rg = tid >> 6;
        const int cg = tid & 63;
        for (int pc = 0; pc < 2; pc++) {
            u64 acc[8][4];
#pragma unroll
            for (int p = 0; p < 8; p++)
#pragma unroll
                for (int j = 0; j < 4; j++) acc[p][j] = 0ull;

#pragma unroll 4
            for (int k = 0; k < 36; k++) {
                const ulonglong2* ap = (const ulonglong2*)(faux + k * SS + rg * 16);
                ulonglong2 A0 = ap[0], A1 = ap[1], A2 = ap[2], A3 = ap[3];
                u64 av[8] = {A0.x, A0.y, A1.x, A1.y, A2.x, A2.y, A3.x, A3.y};
                float4 q = *(const float4*)&wg[k * 512 + pc * 256 + cg * 4];
                float bv[4] = {q.x, q.y, q.z, q.w};
#pragma unroll
                for (int j = 0; j < 4; j++) {
                    u64 bd = dup2(bv[j]);
#pragma unroll
                    for (int p = 0; p < 8; p++) fma2(acc[p][j], av[p], bd);
                }
            }
            float4 cb = *(const float4*)(bg + pc * 256 + cg * 4);
            float bias0[4] = {cb.x, cb.y, cb.z, cb.w};
#pragma unroll
            for (int p = 0; p < 8; p++) {
                int m0 = rowBase + rg * 16 + 2 * p;
                float o0[4], o1[4];
#pragma unroll
                for (int j = 0; j < 4; j++) {
                    unpack2(acc[p][j], o0[j], o1[j]);
                    o0[j] += bias0[j];
                    o1[j] += bias0[j];
                }
                *(float4*)&gx[(size_t)m0 * 512 + pc * 256 + cg * 4] =
                    make_float4(o0[0], o0[1], o0[2], o0[3]);
                *(float4*)&gx[(size_t)(m0 + 1) * 512 + pc * 256 + cg * 4] =
                    make_float4(o1[0], o1[1], o1[2], o1[3]);
            }
        }
    }
}

// ---------------------------------------------------------------------------
// LSTM v9: as v8 but gates phase uses an explicit 8-deep software pipeline on
// the Whh weight loads (hides L1-miss/L2 latency; whT > L1D carveout).
// ---------------------------------------------------------------------------
#define LROWS 32
#define HS_STR 36
#define GS_STR 34

__global__ __launch_bounds__(512) void lstm_v9(
    const float* __restrict__ gx, const int* __restrict__ done,
    const float* __restrict__ h0, const float* __restrict__ c0,
    const float* __restrict__ whT,
    const float* __restrict__ Wa, const float* __restrict__ ba,
    const float* __restrict__ Wc, const float* __restrict__ bc,
    float* __restrict__ out)
{
    extern __shared__ float sm[];
    float* h_s = sm;                        // [HID][HS_STR]
    float* gs  = h_s + HID * HS_STR;        // [512][GS_STR]
    float* msall = gs + 512 * GS_STR;       // [T_LEN*32]
    float* whead = msall + T_LEN * 32;      // [HID*8]
    float* bsh   = whead + HID * 8;         // [8]

    const int tid = threadIdx.x;
    const int r0 = blockIdx.x * LROWS;
    const int r_h = tid / 7;
    const int c_h = tid - r_h * 7;

    float creg[8];
#pragma unroll
    for (int i = 0; i < 8; i++) {
        int e = tid + i * 512;
        int k = e >> 5, r = e & 31;
        h_s[k * HS_STR + r] = h0[(r0 + r) * HID + k];
        creg[i] = c0[(r0 + r) * HID + k];
    }
#pragma unroll
    for (int i = 0; i < 8; i++) {
        int e = tid + i * 512;
        int t = e >> 5, r = e & 31;
        msall[e] = done[t * B_ENV + r0 + r] ? 0.f : 1.f;
    }
    for (int i = tid; i < HID * 8; i += 512) {
        int k = i >> 3, c = i & 7;
        float v = 0.f;
        if (c < NA) v = Wa[k * NA + c];
        else if (c == NA) v = Wc[k];
        whead[i] = v;
    }
    if (tid < 8) bsh[tid] = (tid < NA) ? ba[tid] : ((tid == NA) ? bc[0] : 0.f);
    __syncthreads();

    const float* wp = whT + tid;

    for (int t = 0; t < T_LEN; t++) {
        // ---- gx prefetch for this step ----
        const float* gp = gx + ((size_t)t * B_ENV + r0) * 512 + tid;
        u64 gxp[16];
#pragma unroll
        for (int p = 0; p < 16; p++)
            gxp[p] = pack2(gp[(size_t)(2 * p) * 512], gp[(size_t)(2 * p + 1) * 512]);

        // ---- heads(t-1): warps 0-6 (224 threads), reads h_s only ----
        if (t > 0 && tid < LROWS * 7) {
            float s = bsh[c_h];
#pragma unroll 8
            for (int k = 0; k < HID; k++)
                s += h_s[k * HS_STR + r_h] * whead[k * 8 + c_h];
            out[((size_t)(t - 1) * B_ENV + r0) * 7 + tid] = s;
        }

        // ---- gates: 8-deep SW-pipelined weight loads + FMA2 matvec ----
        {
            u64 macc[16];
#pragma unroll
            for (int p = 0; p < 16; p++) macc[p] = 0ull;

            float wbuf[8];
#pragma unroll
            for (int s = 0; s < 8; s++) wbuf[s] = wp[(size_t)s * 512];

            for (int k8 = 0; k8 < 16; k8++) {
                float wn[8];
                if (k8 < 15) {
#pragma unroll
                    for (int s = 0; s < 8; s++)
                        wn[s] = wp[(size_t)((k8 + 1) * 8 + s) * 512];
                }
#pragma unroll
                for (int s = 0; s < 8; s++) {
                    const int k = k8 * 8 + s;
                    u64 wd = dup2(wbuf[s]);
                    const ulonglong2* hp = (const ulonglong2*)(h_s + k * HS_STR);
                    ulonglong2 H0 = hp[0], H1 = hp[1], H2 = hp[2], H3 = hp[3];
                    ulonglong2 H4 = hp[4], H5 = hp[5], H6 = hp[6], H7 = hp[7];
                    fma2(macc[0], wd, H0.x);  fma2(macc[1], wd, H0.y);
                    fma2(macc[2], wd, H1.x);  fma2(macc[3], wd, H1.y);
                    fma2(macc[4], wd, H2.x);  fma2(macc[5], wd, H2.y);
                    fma2(macc[6], wd, H3.x);  fma2(macc[7], wd, H3.y);
                    fma2(macc[8], wd, H4.x);  fma2(macc[9], wd, H4.y);
                    fma2(macc[10], wd, H5.x); fma2(macc[11], wd, H5.y);
                    fma2(macc[12], wd, H6.x); fma2(macc[13], wd, H6.y);
                    fma2(macc[14], wd, H7.x); fma2(macc[15], wd, H7.y);
                }
                if (k8 < 15) {
#pragma unroll
                    for (int s = 0; s < 8; s++) wbuf[s] = wn[s];
                }
            }
            const float* ms = &msall[t * 32];
#pragma unroll
            for (int p = 0; p < 16; p++) {
                u64 mp = pack2(ms[2 * p], ms[2 * p + 1]);
                *(u64*)&gs[tid * GS_STR + 2 * p] = fma2o(macc[p], mp, gxp[p]);
            }
        }
        __syncthreads();

        // ---- update ----
#pragma unroll
        for (int i = 0; i < 8; i++) {
            int e = tid + i * 512;
            int k = e >> 5, r = e & 31;
            float m = msall[t * 32 + r];
            float ig = gs[k * GS_STR + r];
            float fg = gs[(HID + k) * GS_STR + r];
            float gg = gs[(2 * HID + k) * GS_STR + r];
            float og = gs[(3 * HID + k) * GS_STR + r];
            float c = fsig(fg) * (creg[i] * m) + fsig(ig) * ftanh(gg);
            creg[i] = c;
            h_s[k * HS_STR + r] = fsig(og) * ftanh(c);
        }
        __syncthreads();
    }

    // ---- final heads (t = T_LEN-1) ----
    if (tid < LROWS * 7) {
        float s = bsh[c_h];
#pragma unroll 8
        for (int k = 0; k < HID; k++)
            s += h_s[k * HS_STR + r_h] * whead[k * 8 + c_h];
        out[((size_t)(T_LEN - 1) * B_ENV + r0) * 7 + tid] = s;
    }
}

// ---------------------------------------------------------------------------
// Launch
// ---------------------------------------------------------------------------
extern "C" void kernel_launch(void* const* d_in, const int* in_sizes, int n_in,
                              void* d_out, int out_size)
{
    const float* image = (const float*)d_in[0];
    const float* location = (const float*)d_in[1];
    const float* energy = (const float*)d_in[2];
    const int*   done  = (const int*)d_in[3];
    const float* h0 = (const float*)d_in[4];
    const float* c0 = (const float*)d_in[5];
    const float* W1 = (const float*)d_in[6];
    const float* b1 = (const float*)d_in[7];
    const float* W2 = (const float*)d_in[8];
    const float* b2 = (const float*)d_in[9];
    const float* W3 = (const float*)d_in[10];
    const float* b3 = (const float*)d_in[11];
    const float* W4 = (const float*)d_in[12];
    const float* b4 = (const float*)d_in[13];
    const float* Wl = (const float*)d_in[14];
    const float* bl = (const float*)d_in[15];
    const float* We = (const float*)d_in[16];
    const float* be = (const float*)d_in[17];
    const float* Wih = (const float*)d_in[18];
    const float* Whh = (const float*)d_in[19];
    const float* bih = (const float*)d_in[20];
    const float* bhh = (const float*)d_in[21];
    const float* Wa = (const float*)d_in[22];
    const float* ba = (const float*)d_in[23];
    const float* Wc = (const float*)d_in[24];
    const float* bc = (const float*)d_in[25];
    float* out = (float*)d_out;

    float *pgx, *pwg, *pbg, *pwhT;
    cudaGetSymbolAddress((void**)&pgx, g_gx);
    cudaGetSymbolAddress((void**)&pwg, g_wg);
    cudaGetSymbolAddress((void**)&pbg, g_bg);
    cudaGetSymbolAddress((void**)&pwhT, g_whT);

    prep_wg<<<(36 * 512 + 255) / 256, 256>>>(Wih, Wl, We, pwg);
    prep_bg<<<2, 256>>>(Wih, bl, be, bih, bhh, pbg);
    prep_whT<<<(HID * 512 + 255) / 256, 256>>>(Whh, pwhT);

    const int smemM = (256 * SS + 36 * SS + 32 * 264) * 4;   // 187,968 B
    const int smemL = (HID * HS_STR + 512 * GS_STR + T_LEN * 32 + HID * 8 + 8) * 4;
    cudaFuncSetAttribute(mega_enc, cudaFuncAttributeMaxDynamicSharedMemorySize, smemM);
    cudaFuncSetAttribute(lstm_v9, cudaFuncAttributeMaxDynamicSharedMemorySize, smemL);

    mega_enc<<<N_TOT / 128, 512, smemM>>>(image, location, energy,
                                          W1, b1, W2, b2, W3, b3, W4, b4,
                                          pwg, pbg, pgx);
    lstm_v9<<<B_ENV / LROWS, 512, smemL>>>(pgx, done, h0, c0, pwhT,
                                           Wa, ba, Wc, bc, out);
}

// round 16
// speedup vs baseline: 1.7814x; 1.1099x over previous
#include <cuda_runtime.h>
#include <math.h>
#include <stdint.h>

// Problem constants (fixed by the reference)
#define T_LEN 128
#define B_ENV 4096
#define N_TOT (T_LEN * B_ENV)   // 524288
#define HID   128
#define NA    6

// ---------------------------------------------------------------------------
// Scratch (device globals — no runtime allocation allowed)
// ---------------------------------------------------------------------------
__device__ float g_gx[(size_t)N_TOT * 512];   // 1 GB  precomputed x-gates (fp32)
__device__ float g_wg[36 * 512];              // combined gx weight, k-major
__device__ float g_bg[512];                   // combined gate bias
__device__ float g_whT[HID * 512];            // Whh transposed: [k][j]

// ---------------------------------------------------------------------------
// Packed f32x2 helpers
// ---------------------------------------------------------------------------
typedef unsigned long long u64;
__device__ __forceinline__ u64 pack2(float lo, float hi) {
    u64 r; asm("mov.b64 %0, {%1, %2};" : "=l"(r) : "f"(lo), "f"(hi)); return r;
}
__device__ __forceinline__ u64 dup2(float x) {
    u64 r; asm("mov.b64 %0, {%1, %1};" : "=l"(r) : "f"(x)); return r;
}
__device__ __forceinline__ void fma2(u64& acc, u64 a, u64 b) {
    asm("fma.rn.f32x2 %0, %1, %2, %0;" : "+l"(acc) : "l"(a), "l"(b));
}
__device__ __forceinline__ u64 fma2o(u64 a, u64 b, u64 c) {
    u64 r; asm("fma.rn.f32x2 %0, %1, %2, %3;" : "=l"(r) : "l"(a), "l"(b), "l"(c));
    return r;
}
__device__ __forceinline__ void unpack2(u64 v, float& lo, float& hi) {
    asm("mov.b64 {%0, %1}, %2;" : "=f"(lo), "=f"(hi) : "l"(v));
}
// Hardware tanh (MUFU.TANH, sm_75+ base ISA)
__device__ __forceinline__ float ftanh(float x) {
    float y; asm("tanh.approx.f32 %0, %1;" : "=f"(y) : "f"(x)); return y;
}
__device__ __forceinline__ float fsig(float x) {
    return fmaf(0.5f, ftanh(0.5f * x), 0.5f);
}

// ---------------------------------------------------------------------------
// Weight prep
// ---------------------------------------------------------------------------
__global__ void prep_wg(const float* __restrict__ Wih, const float* __restrict__ Wl,
                        const float* __restrict__ We, float* __restrict__ out)
{
    int idx = blockIdx.x * 256 + threadIdx.x;
    if (idx >= 36 * 512) return;
    int k = idx >> 9, n = idx & 511;
    float v = 0.f;
    if (k < 32) {
        v = Wih[n * 96 + k];
    } else if (k < 34) {
        int d = k - 32;
        float s = 0.f;
        for (int j = 0; j < 32; j++) s += Wl[d * 32 + j] * Wih[n * 96 + 32 + j];
        v = s * 0.1f;
    } else if (k == 34) {
        float s = 0.f;
        for (int j = 0; j < 32; j++) s += We[j] * Wih[n * 96 + 64 + j];
        v = s * (1.f / 200.f);
    }
    out[k * 512 + n] = v;
}

__global__ void prep_bg(const float* __restrict__ Wih, const float* __restrict__ bl,
                        const float* __restrict__ be, const float* __restrict__ bih,
                        const float* __restrict__ bhh, float* __restrict__ bg)
{
    int n = blockIdx.x * 256 + threadIdx.x;
    if (n >= 512) return;
    float s = bih[n] + bhh[n];
    for (int j = 0; j < 32; j++)
        s += bl[j] * Wih[n * 96 + 32 + j] + be[j] * Wih[n * 96 + 64 + j];
    bg[n] = s;
}

__global__ void prep_whT(const float* __restrict__ Whh, float* __restrict__ whT)
{
    int idx = blockIdx.x * 256 + threadIdx.x;
    if (idx >= HID * 512) return;
    int k = idx >> 9, j = idx & 511;
    whT[idx] = Whh[j * HID + k];
}

// ---------------------------------------------------------------------------
// MEGA encoder (unchanged from 5459us best)
// ---------------------------------------------------------------------------
#define SS 132

__global__ __launch_bounds__(512) void mega_enc(
    const float* __restrict__ img, const float* __restrict__ loc,
    const float* __restrict__ eng,
    const float* __restrict__ W1, const float* __restrict__ b1,
    const float* __restrict__ W2, const float* __restrict__ b2,
    const float* __restrict__ W3, const float* __restrict__ b3,
    const float* __restrict__ W4, const float* __restrict__ b4,
    const float* __restrict__ wg, const float* __restrict__ bg,
    float* __restrict__ gx)
{
    extern __shared__ float sm[];
    float* fA   = sm;                    // [256][SS]
    float* faux = fA + 256 * SS;         // [36][SS]
    float* bs   = faux + 36 * SS;        // [32][264]

    const int tid = threadIdx.x;
    const int rowBase = blockIdx.x * 128;

    for (int i = tid; i < 128 * 25; i += 512) {
        int k = i % 25, m = i / 25;
        faux[k * SS + m] = img[(size_t)(rowBase + m) * 25 + k] * (1.f / 255.f);
    }
    for (int i = tid; i < 25 * 256; i += 512) {
        int k = i >> 8, n = i & 255;
        bs[k * 264 + n] = W1[i];
    }
    __syncthreads();

    // ================= phase 1: f1 = relu(x @ W1 + b1), K=25 =================
    {
        const int rg = tid >> 6;
        const int cg = tid & 63;
        u64 acc[8][4];
#pragma unroll
        for (int p = 0; p < 8; p++)
#pragma unroll
            for (int j = 0; j < 4; j++) acc[p][j] = 0ull;

        for (int k = 0; k < 25; k++) {
            const ulonglong2* ap = (const ulonglong2*)(faux + k * SS + rg * 16);
            ulonglong2 A0 = ap[0], A1 = ap[1], A2 = ap[2], A3 = ap[3];
            u64 av[8] = {A0.x, A0.y, A1.x, A1.y, A2.x, A2.y, A3.x, A3.y};
            float4 q = *(const float4*)(bs + k * 264 + cg * 4);
            float bv[4] = {q.x, q.y, q.z, q.w};
#pragma unroll
            for (int j = 0; j < 4; j++) {
                u64 bd = dup2(bv[j]);
#pragma unroll
                for (int p = 0; p < 8; p++) fma2(acc[p][j], av[p], bd);
            }
        }
        float4 c1 = *(const float4*)(b1 + cg * 4);
        float bias1[4] = {c1.x, c1.y, c1.z, c1.w};
        __syncthreads();
#pragma unroll
        for (int p = 0; p < 8; p++) {
            int m0 = rg * 16 + 2 * p;
#pragma unroll
            for (int j = 0; j < 4; j++) {
                float o0, o1;
                unpack2(acc[p][j], o0, o1);
                o0 = fmaxf(o0 + bias1[j], 0.f);
                o1 = fmaxf(o1 + bias1[j], 0.f);
                *(u64*)&fA[(cg * 4 + j) * SS + m0] = pack2(o0, o1);
            }
        }
    }

    // ================= phase 2: f2 = relu(f1 @ W2 + b2), K=256 ================
    {
        const int rg = tid >> 6;
        const int cg = tid & 63;
        float ldr[8];
#define LOADW2(c)                                                      \
    _Pragma("unroll") for (int i = 0; i < 8; i++) {                    \
        int idx = tid + i * 512;                                       \
        int k = idx >> 8, n = idx & 255;                               \
        ldr[i] = W2[(size_t)((c) * 16 + k) * 256 + n];                 \
    }
#define STW2(buf)                                                      \
    _Pragma("unroll") for (int i = 0; i < 8; i++) {                    \
        int idx = tid + i * 512;                                       \
        int k = idx >> 8, n = idx & 255;                               \
        bs[((buf) * 16 + k) * 264 + n] = ldr[i];                       \
    }
        LOADW2(0);
        __syncthreads();
        STW2(0);
        __syncthreads();

        u64 acc[8][4];
#pragma unroll
        for (int p = 0; p < 8; p++)
#pragma unroll
            for (int j = 0; j < 4; j++) acc[p][j] = 0ull;

        for (int c = 0; c < 16; c++) {
            if (c < 15) { LOADW2(c + 1); }
            const float* bsc = bs + (c & 1) * 16 * 264;
            const float* f1c = fA + c * 16 * SS;
#pragma unroll
            for (int k = 0; k < 16; k++) {
                const ulonglong2* ap = (const ulonglong2*)(f1c + k * SS + rg * 16);
                ulonglong2 A0 = ap[0], A1 = ap[1], A2 = ap[2], A3 = ap[3];
                u64 av[8] = {A0.x, A0.y, A1.x, A1.y, A2.x, A2.y, A3.x, A3.y};
                float4 q = *(const float4*)(bsc + k * 264 + cg * 4);
                float bv[4] = {q.x, q.y, q.z, q.w};
#pragma unroll
                for (int j = 0; j < 4; j++) {
                    u64 bd = dup2(bv[j]);
#pragma unroll
                    for (int p = 0; p < 8; p++) fma2(acc[p][j], av[p], bd);
                }
            }
            if (c < 15) { STW2((c + 1) & 1); }
            __syncthreads();
        }
#undef LOADW2
#undef STW2
        float4 c2 = *(const float4*)(b2 + cg * 4);
        float bias2[4] = {c2.x, c2.y, c2.z, c2.w};
#pragma unroll
        for (int p = 0; p < 8; p++) {
            int m0 = rg * 16 + 2 * p;
#pragma unroll
            for (int j = 0; j < 4; j++) {
                float o0, o1;
                unpack2(acc[p][j], o0, o1);
                o0 = fmaxf(o0 + bias2[j], 0.f);
                o1 = fmaxf(o1 + bias2[j], 0.f);
                *(u64*)&fA[(cg * 4 + j) * SS + m0] = pack2(o0, o1);
            }
        }
    }
    __syncthreads();

    // ================= phase 3: f3 = relu(f2 @ W3 + b3), K=256 ================
    {
        const int rg = tid >> 5;
        const int cg = tid & 31;
        float ldr[4];
#define LOADW3(c)                                                      \
    _Pragma("unroll") for (int i = 0; i < 4; i++) {                    \
        int idx = tid + i * 512;                                       \
        int k = idx >> 7, n = idx & 127;                               \
        ldr[i] = W3[(size_t)((c) * 16 + k) * 128 + n];                 \
    }
#define STW3(buf)                                                      \
    _Pragma("unroll") for (int i = 0; i < 4; i++) {                    \
        int idx = tid + i * 512;                                       \
        int k = idx >> 7, n = idx & 127;                               \
        bs[((buf) * 16 + k) * 132 + n] = ldr[i];                       \
    }
        LOADW3(0);
        STW3(0);
        __syncthreads();

        u64 acc[4][4];
#pragma unroll
        for (int p = 0; p < 4; p++)
#pragma unroll
            for (int j = 0; j < 4; j++) acc[p][j] = 0ull;

        for (int c = 0; c < 16; c++) {
            if (c < 15) { LOADW3(c + 1); }
            const float* bsc = bs + (c & 1) * 16 * 132;
            const float* f2c = fA + c * 16 * SS;
#pragma unroll
            for (int k = 0; k < 16; k++) {
                const ulonglong2* ap = (const ulonglong2*)(f2c + k * SS + rg * 8);
                ulonglong2 A0 = ap[0], A1 = ap[1];
                u64 av[4] = {A0.x, A0.y, A1.x, A1.y};
                float4 q = *(const float4*)(bsc + k * 132 + cg * 4);
                float bv[4] = {q.x, q.y, q.z, q.w};
#pragma unroll
                for (int j = 0; j < 4; j++) {
                    u64 bd = dup2(bv[j]);
#pragma unroll
                    for (int p = 0; p < 4; p++) fma2(acc[p][j], av[p], bd);
                }
            }
            if (c < 15) { STW3((c + 1) & 1); }
            __syncthreads();
        }
#undef LOADW3
#undef STW3
        float4 cb = *(const float4*)(b3 + cg * 4);
        float bias3[4] = {cb.x, cb.y, cb.z, cb.w};
#pragma unroll
        for (int p = 0; p < 4; p++) {
            int m0 = rg * 8 + 2 * p;
#pragma unroll
            for (int j = 0; j < 4; j++) {
                float o0, o1;
                unpack2(acc[p][j], o0, o1);
                o0 = fmaxf(o0 + bias3[j], 0.f);
                o1 = fmaxf(o1 + bias3[j], 0.f);
                *(u64*)&fA[(cg * 4 + j) * SS + m0] = pack2(o0, o1);
            }
        }
    }
    __syncthreads();

    // ================= phase 4: f4 = relu(f3 @ W4 + b4), K=128 ================
    {
        const int tr4 = tid >> 3;
        const int tc4 = tid & 7;
        u64 acc[4] = {0ull, 0ull, 0ull, 0ull};
#pragma unroll 4
        for (int k = 0; k < 128; k++) {
            u64 a = *(const u64*)&fA[k * SS + tr4 * 2];
            float4 q = *(const float4*)&W4[k * 32 + tc4 * 4];
            float bv[4] = {q.x, q.y, q.z, q.w};
#pragma unroll
            for (int j = 0; j < 4; j++) fma2(acc[j], a, dup2(bv[j]));
        }
        float4 cb = *(const float4*)(b4 + tc4 * 4);
        float bias4[4] = {cb.x, cb.y, cb.z, cb.w};
        __syncthreads();
#pragma unroll
        for (int j = 0; j < 4; j++) {
            float o0, o1;
            unpack2(acc[j], o0, o1);
            o0 = fmaxf(o0 + bias4[j], 0.f);
            o1 = fmaxf(o1 + bias4[j], 0.f);
            *(u64*)&faux[(tc4 * 4 + j) * SS + tr4 * 2] = pack2(o0, o1);
        }
        if (tid < 128) {
            int n = rowBase + tid;
            faux[32 * SS + tid] = loc[2 * n];
            faux[33 * SS + tid] = loc[2 * n + 1];
            faux[34 * SS + tid] = eng[n];
            faux[35 * SS + tid] = 0.f;
        }
    }
    __syncthreads();

    // ================= phase gx: gates = f4e @ Wg + bg, K=36 ==================
    {
        const int rg = tid >> 6;
        const int cg = tid & 63;
        for (int pc = 0; pc < 2; pc++) {
            u64 acc[8][4];
#pragma unroll
            for (int p = 0; p < 8; p++)
#pragma unroll
                for (int j = 0; j < 4; j++) acc[p][j] = 0ull;

#pragma unroll 4
            for (int k = 0; k < 36; k++) {
                const ulonglong2* ap = (const ulonglong2*)(faux + k * SS + rg * 16);
                ulonglong2 A0 = ap[0], A1 = ap[1], A2 = ap[2], A3 = ap[3];
                u64 av[8] = {A0.x, A0.y, A1.x, A1.y, A2.x, A2.y, A3.x, A3.y};
                float4 q = *(const float4*)&wg[k * 512 + pc * 256 + cg * 4];
                float bv[4] = {q.x, q.y, q.z, q.w};
#pragma unroll
                for (int j = 0; j < 4; j++) {
                    u64 bd = dup2(bv[j]);
#pragma unroll
                    for (int p = 0; p < 8; p++) fma2(acc[p][j], av[p], bd);
                }
            }
            float4 cb = *(const float4*)(bg + pc * 256 + cg * 4);
            float bias0[4] = {cb.x, cb.y, cb.z, cb.w};
#pragma unroll
            for (int p = 0; p < 8; p++) {
                int m0 = rowBase + rg * 16 + 2 * p;
                float o0[4], o1[4];
#pragma unroll
                for (int j = 0; j < 4; j++) {
                    unpack2(acc[p][j], o0[j], o1[j]);
                    o0[j] += bias0[j];
                    o1[j] += bias0[j];
                }
                *(float4*)&gx[(size_t)m0 * 512 + pc * 256 + cg * 4] =
                    make_float4(o0[0], o0[1], o0[2], o0[3]);
                *(float4*)&gx[(size_t)(m0 + 1) * 512 + pc * 256 + cg * 4] =
                    make_float4(o1[0], o1[1], o1[2], o1[3]);
            }
        }
    }
}

// ---------------------------------------------------------------------------
// LSTM v10: 16 rows/CTA, 256 threads, 2 CTAs/SM (grid 256 covers all SMs and
// cross-CTA overlap hides barrier/update bubbles). Each thread owns 2 gate
// columns (tid, tid+256) x 16 rows. Heads fused (warps 0-3, 112 threads).
// ---------------------------------------------------------------------------
#define LROWS 16
#define HS_STR 20   // floats; 80B rows, 16B-aligned
#define GS_STR 18   // floats; 72B rows, 8B-aligned u64 stores

__global__ __launch_bounds__(256, 2) void lstm_v10(
    const float* __restrict__ gx, const int* __restrict__ done,
    const float* __restrict__ h0, const float* __restrict__ c0,
    const float* __restrict__ whT,
    const float* __restrict__ Wa, const float* __restrict__ ba,
    const float* __restrict__ Wc, const float* __restrict__ bc,
    float* __restrict__ out)
{
    extern __shared__ float sm[];
    float* h_s   = sm;                      // [HID][HS_STR]   10240 B
    float* gs    = h_s + HID * HS_STR;      // [512][GS_STR]   36864 B
    float* msall = gs + 512 * GS_STR;       // [T_LEN*16]       8192 B
    float* whead = msall + T_LEN * 16;      // [HID*8]          4096 B
    float* bsh   = whead + HID * 8;         // [8]

    const int tid = threadIdx.x;            // 256 threads
    const int r0 = blockIdx.x * LROWS;
    const int r_h = tid / 7;                // head row (valid tid<112)
    const int c_h = tid - r_h * 7;

    float creg[8];
#pragma unroll
    for (int i = 0; i < 8; i++) {
        int e = tid + i * 256;              // 0..2047
        int k = e >> 4, r = e & 15;
        h_s[k * HS_STR + r] = h0[(r0 + r) * HID + k];
        creg[i] = c0[(r0 + r) * HID + k];
    }
#pragma unroll
    for (int i = 0; i < 8; i++) {
        int e = tid + i * 256;
        int t = e >> 4, r = e & 15;
        msall[e] = done[t * B_ENV + r0 + r] ? 0.f : 1.f;
    }
#pragma unroll
    for (int i = 0; i < 4; i++) {
        int e = tid + i * 256;              // HID*8 = 1024
        int k = e >> 3, c = e & 7;
        float v = 0.f;
        if (c < NA) v = Wa[k * NA + c];
        else if (c == NA) v = Wc[k];
        whead[e] = v;
    }
    if (tid < 8) bsh[tid] = (tid < NA) ? ba[tid] : ((tid == NA) ? bc[0] : 0.f);
    __syncthreads();

    const float* wp0 = whT + tid;           // column tid
    const float* wp1 = whT + tid + 256;     // column tid+256

    for (int t = 0; t < T_LEN; t++) {
        // ---- gx prefetch: cols tid and tid+256, 8 row-pairs each ----
        const float* gp = gx + ((size_t)t * B_ENV + r0) * 512;
        u64 gxp0[8], gxp1[8];
#pragma unroll
        for (int p = 0; p < 8; p++) {
            gxp0[p] = pack2(gp[(size_t)(2 * p) * 512 + tid],
                            gp[(size_t)(2 * p + 1) * 512 + tid]);
            gxp1[p] = pack2(gp[(size_t)(2 * p) * 512 + tid + 256],
                            gp[(size_t)(2 * p + 1) * 512 + tid + 256]);
        }

        // ---- heads(t-1): 112 threads, reads h_s only ----
        if (t > 0 && tid < LROWS * 7) {
            float s = bsh[c_h];
#pragma unroll 8
            for (int k = 0; k < HID; k++)
                s += h_s[k * HS_STR + r_h] * whead[k * 8 + c_h];
            out[((size_t)(t - 1) * B_ENV + r0) * 7 + tid] = s;
        }

        // ---- gates: 2 columns x 16 rows (8 macc each) ----
        {
            u64 m0[8], m1[8];
#pragma unroll
            for (int p = 0; p < 8; p++) { m0[p] = 0ull; m1[p] = 0ull; }

#pragma unroll 4
            for (int k = 0; k < HID; k++) {
                u64 w0 = dup2(wp0[(size_t)k * 512]);
                u64 w1 = dup2(wp1[(size_t)k * 512]);
                const ulonglong2* hp = (const ulonglong2*)(h_s + k * HS_STR);
                ulonglong2 H0 = hp[0], H1 = hp[1], H2 = hp[2], H3 = hp[3];
                fma2(m0[0], w0, H0.x); fma2(m0[1], w0, H0.y);
                fma2(m0[2], w0, H1.x); fma2(m0[3], w0, H1.y);
                fma2(m0[4], w0, H2.x); fma2(m0[5], w0, H2.y);
                fma2(m0[6], w0, H3.x); fma2(m0[7], w0, H3.y);
                fma2(m1[0], w1, H0.x); fma2(m1[1], w1, H0.y);
                fma2(m1[2], w1, H1.x); fma2(m1[3], w1, H1.y);
                fma2(m1[4], w1, H2.x); fma2(m1[5], w1, H2.y);
                fma2(m1[6], w1, H3.x); fma2(m1[7], w1, H3.y);
            }
            const float* ms = &msall[t * 16];
#pragma unroll
            for (int p = 0; p < 8; p++) {
                u64 mp = pack2(ms[2 * p], ms[2 * p + 1]);
                *(u64*)&gs[tid * GS_STR + 2 * p] = fma2o(m0[p], mp, gxp0[p]);
                *(u64*)&gs[(tid + 256) * GS_STR + 2 * p] = fma2o(m1[p], mp, gxp1[p]);
            }
        }
        __syncthreads();

        // ---- update: 8 elements per thread ----
#pragma unroll
        for (int i = 0; i < 8; i++) {
            int e = tid + i * 256;
            int k = e >> 4, r = e & 15;
            float m = msall[t * 16 + r];
            float ig = gs[k * GS_STR + r];
            float fg = gs[(HID + k) * GS_STR + r];
            float gg = gs[(2 * HID + k) * GS_STR + r];
            float og = gs[(3 * HID + k) * GS_STR + r];
            float c = fsig(fg) * (creg[i] * m) + fsig(ig) * ftanh(gg);
            creg[i] = c;
            h_s[k * HS_STR + r] = fsig(og) * ftanh(c);
        }
        __syncthreads();
    }

    // ---- final heads (t = T_LEN-1) ----
    if (tid < LROWS * 7) {
        float s = bsh[c_h];
#pragma unroll 8
        for (int k = 0; k < HID; k++)
            s += h_s[k * HS_STR + r_h] * whead[k * 8 + c_h];
        out[((size_t)(T_LEN - 1) * B_ENV + r0) * 7 + tid] = s;
    }
}

// ---------------------------------------------------------------------------
// Launch
// ---------------------------------------------------------------------------
extern "C" void kernel_launch(void* const* d_in, const int* in_sizes, int n_in,
                              void* d_out, int out_size)
{
    const float* image = (const float*)d_in[0];
    const float* location = (const float*)d_in[1];
    const float* energy = (const float*)d_in[2];
    const int*   done  = (const int*)d_in[3];
    const float* h0 = (const float*)d_in[4];
    const float* c0 = (const float*)d_in[5];
    const float* W1 = (const float*)d_in[6];
    const float* b1 = (const float*)d_in[7];
    const float* W2 = (const float*)d_in[8];
    const float* b2 = (const float*)d_in[9];
    const float* W3 = (const float*)d_in[10];
    const float* b3 = (const float*)d_in[11];
    const float* W4 = (const float*)d_in[12];
    const float* b4 = (const float*)d_in[13];
    const float* Wl = (const float*)d_in[14];
    const float* bl = (const float*)d_in[15];
    const float* We = (const float*)d_in[16];
    const float* be = (const float*)d_in[17];
    const float* Wih = (const float*)d_in[18];
    const float* Whh = (const float*)d_in[19];
    const float* bih = (const float*)d_in[20];
    const float* bhh = (const float*)d_in[21];
    const float* Wa = (const float*)d_in[22];
    const float* ba = (const float*)d_in[23];
    const float* Wc = (const float*)d_in[24];
    const float* bc = (const float*)d_in[25];
    float* out = (float*)d_out;

    float *pgx, *pwg, *pbg, *pwhT;
    cudaGetSymbolAddress((void**)&pgx, g_gx);
    cudaGetSymbolAddress((void**)&pwg, g_wg);
    cudaGetSymbolAddress((void**)&pbg, g_bg);
    cudaGetSymbolAddress((void**)&pwhT, g_whT);

    prep_wg<<<(36 * 512 + 255) / 256, 256>>>(Wih, Wl, We, pwg);
    prep_bg<<<2, 256>>>(Wih, bl, be, bih, bhh, pbg);
    prep_whT<<<(HID * 512 + 255) / 256, 256>>>(Whh, pwhT);

    const int smemM = (256 * SS + 36 * SS + 32 * 264) * 4;   // 187,968 B
    const int smemL = (HID * HS_STR + 512 * GS_STR + T_LEN * 16 + HID * 8 + 8) * 4; // 59,424 B
    cudaFuncSetAttribute(mega_enc, cudaFuncAttributeMaxDynamicSharedMemorySize, smemM);
    cudaFuncSetAttribute(lstm_v10, cudaFuncAttributeMaxDynamicSharedMemorySize, smemL);

    mega_enc<<<N_TOT / 128, 512, smemM>>>(image, location, energy,
                                          W1, b1, W2, b2, W3, b3, W4, b4,
                                          pwg, pbg, pgx);
    lstm_v10<<<B_ENV / LROWS, 256, smemL>>>(pgx, done, h0, c0, pwhT,
                                            Wa, ba, Wc, bc, out);
}